// round 12
// baseline (speedup 1.0000x reference)
#include <cuda_runtime.h>
#include <cuda_bf16.h>
#include <math.h>
#include <stdint.h>
#include <string.h>

// Problem constants
#define BB   32
#define TT   127
#define SS   256
#define HH   512
#define VV   8000
#define NHH  8
#define HDD  64
#define BT   (BB*TT)      // 4064
#define BS   (BB*SS)      // 8192
#define NBLK 128          // persistent LSTM grid (4 groups x 32 blocks)
#define MPAD 4096
#define VPAD 8064

// ---------------- scratch (device globals; no allocations allowed) ----------------
__device__ float g_xg  [BT * 4 * HH];
__device__ float g_lstm[BT * HH];
__device__ float g_q   [BT * HH];
__device__ float g_kv  [BS * 1024];           // packed K(0..511) | V(512..1023)
__device__ unsigned g_flags[NBLK * 2 * 32];

// bf16 hi/lo split buffers (pads stay zero: device globals zero-init, never written)
__device__ __nv_bfloat16 g_embh [MPAD * HH], g_embl [MPAD * HH];
__device__ __nv_bfloat16 g_lstmh[MPAD * HH], g_lstml[MPAD * HH];
__device__ __nv_bfloat16 g_ctxh [MPAD * HH], g_ctxl [MPAD * HH];
__device__ __nv_bfloat16 g_combh[MPAD * HH], g_combl[MPAD * HH];
__device__ __nv_bfloat16 g_ench [BS * HH],   g_encl [BS * HH];
__device__ __nv_bfloat16 g_wihh [4*HH*HH],   g_wihl [4*HH*HH];
__device__ __nv_bfloat16 g_whhh [4*HH*HH],   g_whhl [4*HH*HH];
__device__ __nv_bfloat16 g_inph [3*HH*HH],   g_inpl [3*HH*HH];
__device__ __nv_bfloat16 g_outph[HH*HH],     g_outpl[HH*HH];
__device__ __nv_bfloat16 g_fcwh [VPAD * HH], g_fcwl [VPAD * HH];
// LSTM h ping-pong, bf16 hi/lo, B-operand packed layout
__device__ __nv_bfloat16 g_hbh[2][4 * 4096];
__device__ __nv_bfloat16 g_hbl[2][4 * 4096];

// ---------------- cp.async helpers ----------------
__device__ __forceinline__ void cp_async16(uint32_t dst_smem, const void* src_gmem) {
    asm volatile("cp.async.cg.shared.global [%0], [%1], 16;\n" :: "r"(dst_smem), "l"(src_gmem));
}
__device__ __forceinline__ void cp_async_commit() { asm volatile("cp.async.commit_group;\n"); }
#define CP_WAITN(n) asm volatile("cp.async.wait_group %0;\n" :: "n"(n))

__device__ __forceinline__ uint32_t s2u(const void* p) {
    uint32_t a;
    asm("{ .reg .u64 t; cvta.to.shared.u64 t, %1; cvt.u32.u64 %0, t; }" : "=r"(a) : "l"(p));
    return a;
}
__device__ __forceinline__ void st_bf16_cg(__nv_bfloat16* p, __nv_bfloat16 v) {
    unsigned short u; memcpy(&u, &v, 2);
    asm volatile("st.global.cg.u16 [%0], %1;" :: "l"(p), "h"(u) : "memory");
}
__device__ __forceinline__ void split1(float v, __nv_bfloat16& h, __nv_bfloat16& l) {
    h = __float2bfloat16_rn(v);
    l = __float2bfloat16_rn(v - __bfloat162float(h));
}

// ---------------- mma helpers ----------------
#define LDSM_X4(r0, r1, r2, r3, addr)                                              \
    asm volatile("ldmatrix.sync.aligned.m8n8.x4.shared.b16 {%0,%1,%2,%3}, [%4];"   \
        : "=r"(r0), "=r"(r1), "=r"(r2), "=r"(r3) : "r"(addr))
#define LDSM_X2(r0, r1, addr)                                                      \
    asm volatile("ldmatrix.sync.aligned.m8n8.x2.shared.b16 {%0,%1}, [%2];"         \
        : "=r"(r0), "=r"(r1) : "r"(addr))
#define MMA16816(d, a, b)                                                          \
    asm volatile("mma.sync.aligned.m16n8k16.row.col.f32.bf16.bf16.f32 "            \
        "{%0,%1,%2,%3},{%4,%5,%6,%7},{%8,%9},{%0,%1,%2,%3};"                       \
        : "+f"((d)[0]), "+f"((d)[1]), "+f"((d)[2]), "+f"((d)[3])                   \
        : "r"((a)[0]), "r"((a)[1]), "r"((a)[2]), "r"((a)[3]),                      \
          "r"((b)[0]), "r"((b)[1]))

// ---------------- init: zero h0 (bf16 buffers) and flags ----------------
__global__ void zero_kernel() {
    int i = blockIdx.x * blockDim.x + threadIdx.x;
    if (i < 2 * 4 * 4096) {
        ((__nv_bfloat16*)g_hbh)[i] = __float2bfloat16(0.f);
        ((__nv_bfloat16*)g_hbl)[i] = __float2bfloat16(0.f);
    }
    if (i < NBLK * 2 * 32) g_flags[i] = 0u;
}

// ---------------- embedding gather fused with hi/lo split ----------------
__global__ void gather_split_kernel(const int* __restrict__ targets,
                                    const float* __restrict__ table,
                                    __nv_bfloat16* __restrict__ hi,
                                    __nv_bfloat16* __restrict__ lo) {
    int bt = blockIdx.x;
    int b = bt / TT, t = bt - b * TT;
    int tok = targets[b * 128 + t];
    int j = threadIdx.x;                      // 0..127, 4 floats each
    float4 v = ((const float4*)(table + (size_t)tok * HH))[j];
    __nv_bfloat16 hx, hy, hz, hw, lx, ly, lz, lw;
    split1(v.x, hx, lx); split1(v.y, hy, ly);
    split1(v.z, hz, lz); split1(v.w, hw, lw);
    size_t o = (size_t)bt * HH + j * 4;
    *(__nv_bfloat162*)(hi + o)     = __halves2bfloat162(hx, hy);
    *(__nv_bfloat162*)(hi + o + 2) = __halves2bfloat162(hz, hw);
    *(__nv_bfloat162*)(lo + o)     = __halves2bfloat162(lx, ly);
    *(__nv_bfloat162*)(lo + o + 2) = __halves2bfloat162(lz, lw);
}

// ---------------- fp32 -> bf16 hi/lo split (weights/enc only) ----------------
__global__ void split_kernel(const float* __restrict__ x,
                             __nv_bfloat16* __restrict__ hi,
                             __nv_bfloat16* __restrict__ lo, int n) {
    int i4 = (blockIdx.x * blockDim.x + threadIdx.x) * 4;
    if (i4 < n) {
        float4 v = *(const float4*)(x + i4);
        __nv_bfloat16 hx, hy, hz, hw, lx, ly, lz, lw;
        split1(v.x, hx, lx); split1(v.y, hy, ly);
        split1(v.z, hz, lz); split1(v.w, hw, lw);
        *(__nv_bfloat162*)(hi + i4)     = __halves2bfloat162(hx, hy);
        *(__nv_bfloat162*)(hi + i4 + 2) = __halves2bfloat162(hz, hw);
        *(__nv_bfloat162*)(lo + i4)     = __halves2bfloat162(lx, ly);
        *(__nv_bfloat162*)(lo + i4 + 2) = __halves2bfloat162(lz, lw);
    }
}

// ---------------- tensor-core GEMM via mma.sync (3xbf16 split) ----------------
// Optional outputs: fp32 C and/or bf16 hi/lo (Chi/Clo) written from the same accumulators.
#define AP   40
#define SEG  (128 * AP * 2)
__global__ __launch_bounds__(256) void mma_gemm(
    const __nv_bfloat16* __restrict__ Ah, const __nv_bfloat16* __restrict__ Al,
    const __nv_bfloat16* __restrict__ Bh, const __nv_bfloat16* __restrict__ Bl,
    const float* __restrict__ bias1, const float* __restrict__ bias2,
    const float* __restrict__ res, float* __restrict__ C,
    __nv_bfloat16* __restrict__ Chi, __nv_bfloat16* __restrict__ Clo,
    int M, int N, int K)
{
    extern __shared__ char smem[];
    const uint32_t sb = s2u(smem);
    const int tid  = threadIdx.x;
    const int wid  = tid >> 5;
    const int lane = tid & 31;
    const int wm = wid >> 2;
    const int wn = wid & 3;
    const int m0 = blockIdx.y * 128;
    const int n0 = blockIdx.x * 128;

    float acc[4][4][4];
    #pragma unroll
    for (int i = 0; i < 4; i++)
        #pragma unroll
        for (int j = 0; j < 4; j++)
            #pragma unroll
            for (int r = 0; r < 4; r++) acc[i][j][r] = 0.f;

    const __nv_bfloat16* srcAh = Ah + (size_t)m0 * K;
    const __nv_bfloat16* srcAl = Al + (size_t)m0 * K;
    const __nv_bfloat16* srcBh = Bh + (size_t)n0 * K;
    const __nv_bfloat16* srcBl = Bl + (size_t)n0 * K;

    auto issue = [&](int k0, int buf) {
        #pragma unroll
        for (int t = 0; t < 8; t++) {
            int idx = tid + t * 256;
            int mat = idx >> 9;
            int r   = (idx >> 2) & 127;
            int j   = idx & 3;
            uint32_t dst = sb + (uint32_t)(mat * 2 + buf) * SEG
                         + (uint32_t)(r * AP + j * 8) * 2;
            const __nv_bfloat16* s =
                (mat == 0 ? srcAh : mat == 1 ? srcAl : mat == 2 ? srcBh : srcBl)
                + (size_t)r * K + k0 + j * 8;
            cp_async16(dst, s);
        }
        cp_async_commit();
    };

    const uint32_t a_off = (uint32_t)(((wm * 64 + (lane & 15)) * AP + (lane >> 4) * 8) * 2);
    const uint32_t b_off = (uint32_t)(((wn * 32 + (lane & 7)) * AP + ((lane >> 3) & 1) * 8) * 2);

    const int NC = K / 32;
    issue(0, 0);
    #pragma unroll 1
    for (int c = 0; c < NC; c++) {
        const int buf = c & 1;
        if (c + 1 < NC) { issue((c + 1) * 32, buf ^ 1); CP_WAITN(1); }
        else           { CP_WAITN(0); }
        __syncthreads();

        #pragma unroll
        for (int ks = 0; ks < 2; ks++) {
            const uint32_t kb = (uint32_t)(ks * 32);
            uint32_t bh[4][2], bl[4][2];
            #pragma unroll
            for (int nt = 0; nt < 4; nt++) {
                uint32_t ba = sb + (uint32_t)(4 + buf) * SEG + b_off
                            + (uint32_t)(nt * 8 * AP * 2) + kb;
                LDSM_X2(bh[nt][0], bh[nt][1], ba);
                LDSM_X2(bl[nt][0], bl[nt][1], ba + 2u * SEG);
            }
            #pragma unroll
            for (int mt = 0; mt < 4; mt++) {
                uint32_t ah[4], al[4];
                uint32_t aa = sb + (uint32_t)buf * SEG + a_off
                            + (uint32_t)(mt * 16 * AP * 2) + kb;
                LDSM_X4(ah[0], ah[1], ah[2], ah[3], aa);
                LDSM_X4(al[0], al[1], al[2], al[3], aa + 2u * SEG);
                #pragma unroll
                for (int nt = 0; nt < 4; nt++) {
                    MMA16816(acc[mt][nt], ah, bh[nt]);
                    MMA16816(acc[mt][nt], ah, bl[nt]);
                    MMA16816(acc[mt][nt], al, bh[nt]);
                }
            }
        }
        __syncthreads();
    }

    const int tm = lane >> 2;
    const int tc = (lane & 3) * 2;
    #pragma unroll
    for (int mt = 0; mt < 4; mt++) {
        #pragma unroll
        for (int nt = 0; nt < 4; nt++) {
            int col = n0 + wn * 32 + nt * 8 + tc;
            if (col + 2 > N) continue;           // all N are multiples of 128 here
            float2 v0 = make_float2(acc[mt][nt][0], acc[mt][nt][1]);
            float2 v1 = make_float2(acc[mt][nt][2], acc[mt][nt][3]);
            if (bias1) {
                float2 b = *(const float2*)(bias1 + col);
                v0.x += b.x; v0.y += b.y; v1.x += b.x; v1.y += b.y;
            }
            if (bias2) {
                float2 b = *(const float2*)(bias2 + col);
                v0.x += b.x; v0.y += b.y; v1.x += b.x; v1.y += b.y;
            }
            #pragma unroll
            for (int half = 0; half < 2; half++) {
                int row = m0 + wm * 64 + mt * 16 + tm + half * 8;
                if (row >= M) continue;
                float2 o = half ? v1 : v0;
                if (res) {
                    float2 rr = *(const float2*)(res + (size_t)row * N + col);
                    o.x += rr.x; o.y += rr.y;
                }
                if (C) *(float2*)(C + (size_t)row * N + col) = o;
                if (Chi) {
                    __nv_bfloat16 h0, h1, l0, l1;
                    split1(o.x, h0, l0); split1(o.y, h1, l1);
                    *(__nv_bfloat162*)(Chi + (size_t)row * N + col) = __halves2bfloat162(h0, h1);
                    *(__nv_bfloat162*)(Clo + (size_t)row * N + col) = __halves2bfloat162(l0, l1);
                }
            }
        }
    }
}

// ---------------- tensor-core persistent LSTM (R11, + fused hi/lo output) ----------------
#define LW_SEG  (64 * AP * 2)
#define LH_SEG  (8 * AP * 2)
#define SM_WH   0
#define SM_WL   81920
#define SM_HH   163840
#define SM_HL   174080
#define SM_RED  184320
#define LSTM_SMEM (SM_RED + 16 * 513 * 4)

__global__ __launch_bounds__(512) void lstm_mma_kernel(
    const float* __restrict__ xg,
    const __nv_bfloat16* __restrict__ whh_h, const __nv_bfloat16* __restrict__ whh_l,
    float* __restrict__ lstm_out,
    __nv_bfloat16* __restrict__ lstm_h, __nv_bfloat16* __restrict__ lstm_l)
{
    extern __shared__ char smem[];
    const uint32_t sb = s2u(smem);
    float* red = (float*)(smem + SM_RED);

    const int tid   = threadIdx.x;
    const int wid   = tid >> 5;
    const int lane  = tid & 31;
    const int group = blockIdx.x >> 5;
    const int gslot = blockIdx.x & 31;
    const int col_base = gslot * 16;

    for (int it = tid; it < 16 * 64 * 4; it += 512) {
        int s = it >> 8;
        int r = (it >> 2) & 63;
        int j = it & 3;
        int gate = r >> 4, colL = r & 15;
        size_t src = (size_t)(gate * HH + col_base + colL) * HH + s * 32 + j * 8;
        uint32_t dst = (uint32_t)(s * LW_SEG + r * (AP * 2) + j * 16);
        cp_async16(sb + SM_WH + dst, whh_h + src);
        cp_async16(sb + SM_WL + dst, whh_l + src);
    }
    cp_async_commit();
    CP_WAITN(0);
    __syncthreads();

    const int seg = wid;
    const uint32_t a_off = (uint32_t)(((lane & 15) * AP + (lane >> 4) * 8) * 2);
    uint32_t Afh[4][2][4], Afl[4][2][4];
    #pragma unroll
    for (int g = 0; g < 4; g++) {
        #pragma unroll
        for (int ks = 0; ks < 2; ks++) {
            uint32_t aa = sb + (uint32_t)(seg * LW_SEG + g * 16 * AP * 2) + a_off
                        + (uint32_t)(ks * 32);
            LDSM_X4(Afh[g][ks][0], Afh[g][ks][1], Afh[g][ks][2], Afh[g][ks][3], aa);
            LDSM_X4(Afl[g][ks][0], Afl[g][ks][1], Afl[g][ks][2], Afl[g][ks][3],
                    aa + (uint32_t)(SM_WL - SM_WH));
        }
    }

    const uint32_t b_off = (uint32_t)(((lane & 7) * AP + ((lane >> 3) & 1) * 8) * 2);

    const int acolL = tid >> 3;
    const int ab    = tid & 7;
    const int gcol  = col_base + acolL;
    const int abatch = group * 8 + ab;
    const int hseg  = gcol >> 5;
    const int hc32  = gcol & 31;
    const size_t xgb = (size_t)(abatch * TT) * (4 * HH) + gcol;
    unsigned* my_flag = &g_flags[blockIdx.x * 64];
    float c_reg = 0.f;

    const __nv_bfloat16* hbh_rd[2] = { g_hbh[0] + group * 4096, g_hbh[1] + group * 4096 };
    const __nv_bfloat16* hbl_rd[2] = { g_hbl[0] + group * 4096, g_hbl[1] + group * 4096 };
    __nv_bfloat16* hbh_wr[2] = { g_hbh[0] + group * 4096, g_hbh[1] + group * 4096 };
    __nv_bfloat16* hbl_wr[2] = { g_hbl[0] + group * 4096, g_hbl[1] + group * 4096 };

    for (int t = 0; t < TT; t++) {
        const int rb = t & 1;
        const int wb = rb ^ 1;

        if (t > 0) {
            if (tid < 32) {
                const unsigned* fp = &g_flags[(group * 32 + tid) * 64];
                unsigned v;
                do {
                    asm volatile("ld.acquire.gpu.global.u32 %0, [%1];"
                                 : "=r"(v) : "l"(fp) : "memory");
                } while (v < (unsigned)t);
            }
            __syncthreads();
        }

        #pragma unroll
        for (int i = 0; i < 2; i++) {
            int it = tid + i * 512;
            int m  = it >> 9;
            int idx = it & 511;
            int s = idx >> 5, b = (idx >> 2) & 7, j = idx & 3;
            const __nv_bfloat16* src = (m ? hbl_rd[rb] : hbh_rd[rb])
                                     + s * 256 + b * 32 + j * 8;
            uint32_t dst = sb + (uint32_t)(m ? SM_HL : SM_HH)
                         + (uint32_t)(s * LH_SEG + b * (AP * 2) + j * 16);
            cp_async16(dst, src);
        }
        cp_async_commit();

        float xv0 = 0.f, xv1 = 0.f, xv2 = 0.f, xv3 = 0.f;
        if (tid < 128) {
            const float* xp = xg + xgb + (size_t)t * (4 * HH);
            xv0 = __ldg(xp);
            xv1 = __ldg(xp + HH);
            xv2 = __ldg(xp + 2 * HH);
            xv3 = __ldg(xp + 3 * HH);
        }

        CP_WAITN(0);
        __syncthreads();

        float acc[4][4];
        #pragma unroll
        for (int g = 0; g < 4; g++)
            #pragma unroll
            for (int r = 0; r < 4; r++) acc[g][r] = 0.f;

        #pragma unroll
        for (int ks = 0; ks < 2; ks++) {
            uint32_t ba = sb + SM_HH + (uint32_t)(seg * LH_SEG) + b_off + (uint32_t)(ks * 32);
            uint32_t bh[2], bl[2];
            LDSM_X2(bh[0], bh[1], ba);
            LDSM_X2(bl[0], bl[1], ba + (uint32_t)(SM_HL - SM_HH));
            #pragma unroll
            for (int g = 0; g < 4; g++) {
                MMA16816(acc[g], Afh[g][ks], bh);
                MMA16816(acc[g], Afh[g][ks], bl);
                MMA16816(acc[g], Afl[g][ks], bh);
            }
        }

        {
            const int tm = lane >> 2;
            const int tc = (lane & 3) * 2;
            float* rp = red + wid * 513;
            #pragma unroll
            for (int g = 0; g < 4; g++) {
                rp[g * 128 + tm * 8 + tc]           = acc[g][0];
                rp[g * 128 + tm * 8 + tc + 1]       = acc[g][1];
                rp[g * 128 + (tm + 8) * 8 + tc]     = acc[g][2];
                rp[g * 128 + (tm + 8) * 8 + tc + 1] = acc[g][3];
            }
        }
        __syncthreads();

        if (tid < 128) {
            const int p = acolL * 8 + ab;
            float gv[4] = { xv0, xv1, xv2, xv3 };
            #pragma unroll
            for (int w = 0; w < 16; w++) {
                const float* rp = red + w * 513 + p;
                gv[0] += rp[0];
                gv[1] += rp[128];
                gv[2] += rp[256];
                gv[3] += rp[384];
            }
            float ig = 1.f / (1.f + __expf(-gv[0]));
            float fg = 1.f / (1.f + __expf(-gv[1]));
            float gg = tanhf(gv[2]);
            float og = 1.f / (1.f + __expf(-gv[3]));
            c_reg = fg * c_reg + ig * gg;
            float hn = og * tanhf(c_reg);
            size_t oidx = (size_t)(abatch * TT + t) * HH + gcol;
            lstm_out[oidx] = hn;
            __nv_bfloat16 hh_, hl_;
            split1(hn, hh_, hl_);
            lstm_h[oidx] = hh_;          // fused split for q-projection input
            lstm_l[oidx] = hl_;
            int off = hseg * 256 + ab * 32 + hc32;
            st_bf16_cg(hbh_wr[wb] + off, hh_);
            st_bf16_cg(hbl_wr[wb] + off, hl_);
        }
        __syncthreads();

        if (tid == 0) {
            asm volatile("fence.acq_rel.gpu;" ::: "memory");
            asm volatile("st.release.gpu.global.u32 [%0], %1;"
                         :: "l"(my_flag), "r"((unsigned)(t + 1)) : "memory");
        }
    }
}

// ---------------- fused attention (packed kv input, bf16 hi/lo ctx output) ----------------
#define KTP 257
#define QSP 68
#define PSP 260
__global__ __launch_bounds__(256) void attn_kernel(
    const float* __restrict__ q, const float* __restrict__ kv,
    __nv_bfloat16* __restrict__ ctxh, __nv_bfloat16* __restrict__ ctxl)
{
    extern __shared__ float smemf[];
    float* Kt   = smemf;
    float* Vt   = Kt + 64 * KTP;
    float* qs   = Vt + 64 * KTP;
    float* ps   = qs + 32 * QSP;
    float* sums = ps + 32 * PSP;

    const int t0 = blockIdx.x * 32;
    const int h  = blockIdx.y;
    const int b  = blockIdx.z;
    const int tid = threadIdx.x;

    for (int idx = tid; idx < 256 * 16; idx += 256) {
        int s = idx >> 4; int d4 = (idx & 15) << 2;
        size_t off = (size_t)(b * SS + s) * 1024 + h * HDD + d4;
        float4 kvv = *(const float4*)(kv + off);
        Kt[(d4 + 0) * KTP + s] = kvv.x; Kt[(d4 + 1) * KTP + s] = kvv.y;
        Kt[(d4 + 2) * KTP + s] = kvv.z; Kt[(d4 + 3) * KTP + s] = kvv.w;
        float4 vvv = *(const float4*)(kv + off + 512);
        Vt[(d4 + 0) * KTP + s] = vvv.x; Vt[(d4 + 1) * KTP + s] = vvv.y;
        Vt[(d4 + 2) * KTP + s] = vvv.z; Vt[(d4 + 3) * KTP + s] = vvv.w;
    }
    for (int idx = tid; idx < 32 * 16; idx += 256) {
        int r = idx >> 4; int d4 = (idx & 15) << 2;
        int trow = t0 + r;
        float4 qv = make_float4(0.f, 0.f, 0.f, 0.f);
        if (trow < TT)
            qv = *(const float4*)(q + (size_t)(b * TT + trow) * HH + h * HDD + d4);
        float* d = qs + r * QSP + d4;
        d[0] = qv.x; d[1] = qv.y; d[2] = qv.z; d[3] = qv.w;
    }
    __syncthreads();

    const int r  = tid >> 3;
    const int lc = tid & 7;

    float qreg[64];
    #pragma unroll
    for (int d = 0; d < 64; d++) qreg[d] = qs[r * QSP + d];

    float sc[32];
    for (int si = 0; si < 32; si++) {
        int s = si * 8 + lc;
        float acc = 0.f;
        #pragma unroll
        for (int d = 0; d < 64; d++) acc += qreg[d] * Kt[d * KTP + s];
        sc[si] = acc * 0.125f;
    }
    float m = -1e30f;
    #pragma unroll
    for (int si = 0; si < 32; si++) m = fmaxf(m, sc[si]);
    m = fmaxf(m, __shfl_xor_sync(0xffffffff, m, 1));
    m = fmaxf(m, __shfl_xor_sync(0xffffffff, m, 2));
    m = fmaxf(m, __shfl_xor_sync(0xffffffff, m, 4));
    float ssum = 0.f;
    #pragma unroll
    for (int si = 0; si < 32; si++) {
        float e = __expf(sc[si] - m);
        ssum += e;
        ps[r * PSP + si * 8 + lc] = e;
    }
    ssum += __shfl_xor_sync(0xffffffff, ssum, 1);
    ssum += __shfl_xor_sync(0xffffffff, ssum, 2);
    ssum += __shfl_xor_sync(0xffffffff, ssum, 4);
    if (lc == 0) sums[r] = ssum;
    __syncthreads();

    float accv[8];
    #pragma unroll
    for (int j = 0; j < 8; j++) accv[j] = 0.f;
    const float* prow = ps + r * PSP;
    #pragma unroll 4
    for (int s = 0; s < 256; s++) {
        float pv = prow[s];
        #pragma unroll
        for (int j = 0; j < 8; j++)
            accv[j] += pv * Vt[(lc + 8 * j) * KTP + s];
    }
    float inv = 1.0f / sums[r];
    int trow = t0 + r;
    if (trow < TT) {
        size_t base = (size_t)(b * TT + trow) * HH + h * HDD;
        #pragma unroll
        for (int j = 0; j < 8; j++) {
            float val = accv[j] * inv;
            __nv_bfloat16 hv, lv;
            split1(val, hv, lv);
            ctxh[base + lc + 8 * j] = hv;
            ctxl[base + lc + 8 * j] = lv;
        }
    }
}

// ---------------- launch ----------------
extern "C" void kernel_launch(void* const* d_in, const int* in_sizes, int n_in,
                              void* d_out, int out_size) {
    const int*   targets  = (const int*)  d_in[0];
    const float* enc      = (const float*)d_in[1];
    const float* embedding= (const float*)d_in[2];
    const float* w_ih     = (const float*)d_in[3];
    const float* w_hh     = (const float*)d_in[4];
    const float* b_ih     = (const float*)d_in[5];
    const float* b_hh     = (const float*)d_in[6];
    const float* in_proj_w= (const float*)d_in[7];
    const float* in_proj_b= (const float*)d_in[8];
    const float* out_proj_w=(const float*)d_in[9];
    const float* out_proj_b=(const float*)d_in[10];
    const float* fc_w     = (const float*)d_in[11];
    const float* fc_b     = (const float*)d_in[12];
    float* out = (float*)d_out;

    float *p_xg, *p_lstm, *p_q, *p_kv;
    cudaGetSymbolAddress((void**)&p_xg,   g_xg);
    cudaGetSymbolAddress((void**)&p_lstm, g_lstm);
    cudaGetSymbolAddress((void**)&p_q,    g_q);
    cudaGetSymbolAddress((void**)&p_kv,   g_kv);
    __nv_bfloat16 *p_embh, *p_embl, *p_lstmh, *p_lstml, *p_ctxh, *p_ctxl,
                  *p_combh, *p_combl, *p_ench, *p_encl, *p_wihh, *p_wihl,
                  *p_whhh, *p_whhl, *p_inph, *p_inpl, *p_outph, *p_outpl,
                  *p_fcwh, *p_fcwl;
    cudaGetSymbolAddress((void**)&p_embh,  g_embh);
    cudaGetSymbolAddress((void**)&p_embl,  g_embl);
    cudaGetSymbolAddress((void**)&p_lstmh, g_lstmh);
    cudaGetSymbolAddress((void**)&p_lstml, g_lstml);
    cudaGetSymbolAddress((void**)&p_ctxh,  g_ctxh);
    cudaGetSymbolAddress((void**)&p_ctxl,  g_ctxl);
    cudaGetSymbolAddress((void**)&p_combh, g_combh);
    cudaGetSymbolAddress((void**)&p_combl, g_combl);
    cudaGetSymbolAddress((void**)&p_ench,  g_ench);
    cudaGetSymbolAddress((void**)&p_encl,  g_encl);
    cudaGetSymbolAddress((void**)&p_wihh,  g_wihh);
    cudaGetSymbolAddress((void**)&p_wihl,  g_wihl);
    cudaGetSymbolAddress((void**)&p_whhh,  g_whhh);
    cudaGetSymbolAddress((void**)&p_whhl,  g_whhl);
    cudaGetSymbolAddress((void**)&p_inph,  g_inph);
    cudaGetSymbolAddress((void**)&p_inpl,  g_inpl);
    cudaGetSymbolAddress((void**)&p_outph, g_outph);
    cudaGetSymbolAddress((void**)&p_outpl, g_outpl);
    cudaGetSymbolAddress((void**)&p_fcwh,  g_fcwh);
    cudaGetSymbolAddress((void**)&p_fcwl,  g_fcwl);

    const int attn_smem = (64 * KTP * 2 + 32 * QSP + 32 * PSP + 32) * (int)sizeof(float);
    const int mma_smem  = 8 * SEG;
    cudaFuncSetAttribute(attn_kernel,     cudaFuncAttributeMaxDynamicSharedMemorySize, attn_smem);
    cudaFuncSetAttribute(mma_gemm,        cudaFuncAttributeMaxDynamicSharedMemorySize, mma_smem);
    cudaFuncSetAttribute(lstm_mma_kernel, cudaFuncAttributeMaxDynamicSharedMemorySize, LSTM_SMEM);

    #define SPLIT(src, hi, lo, n) split_kernel<<<((n)/4 + 255) / 256, 256>>>(src, hi, lo, n)

    // 1. zero h0 + flags
    zero_kernel<<<(2 * 4 * 4096 + 255) / 256, 256>>>();

    // 2. weight/input splits (activations are split by their producers)
    SPLIT(w_ih,       p_wihh,  p_wihl,  4 * HH * HH);
    SPLIT(w_hh,       p_whhh,  p_whhl,  4 * HH * HH);
    SPLIT(in_proj_w,  p_inph,  p_inpl,  3 * HH * HH);
    SPLIT(out_proj_w, p_outph, p_outpl, HH * HH);
    SPLIT(fc_w,       p_fcwh,  p_fcwl,  VV * HH);
    SPLIT(enc,        p_ench,  p_encl,  BS * HH);

    // 3. gather embeddings (fused split)
    gather_split_kernel<<<BT, 128>>>(targets, embedding, p_embh, p_embl);

    // 4. xg = emb @ w_ih^T + b_ih + b_hh
    {
        dim3 grid(4 * HH / 128, MPAD / 128);
        mma_gemm<<<grid, 256, mma_smem>>>(p_embh, p_embl, p_wihh, p_wihl,
                                          b_ih, b_hh, nullptr, p_xg, nullptr, nullptr,
                                          BT, 4 * HH, HH);
    }

    // 5. LSTM recurrence (emits fp32 + bf16 hi/lo)
    lstm_mma_kernel<<<NBLK, 512, LSTM_SMEM>>>(p_xg, p_whhh, p_whhl,
                                              p_lstm, p_lstmh, p_lstml);

    // 6. q projection + merged K|V projection (wk,wv are contiguous in in_proj_w)
    {
        dim3 gq(HH / 128, MPAD / 128);
        mma_gemm<<<gq, 256, mma_smem>>>(p_lstmh, p_lstml, p_inph, p_inpl,
                                        in_proj_b, nullptr, nullptr, p_q, nullptr, nullptr,
                                        BT, HH, HH);
        dim3 gkv(1024 / 128, BS / 128);
        mma_gemm<<<gkv, 256, mma_smem>>>(p_ench, p_encl, p_inph + (size_t)HH * HH,
                                         p_inpl + (size_t)HH * HH,
                                         in_proj_b + HH, nullptr, nullptr, p_kv,
                                         nullptr, nullptr, BS, 1024, HH);
    }

    // 7. fused attention -> ctx hi/lo (split fused)
    {
        dim3 grid(4, NHH, BB);
        attn_kernel<<<grid, 256, attn_smem>>>(p_q, p_kv, p_ctxh, p_ctxl);
    }

    // 8. combined = ctx @ out_proj^T + out_proj_b + lstm_out  (direct bf16 hi/lo output)
    {
        dim3 grid(HH / 128, MPAD / 128);
        mma_gemm<<<grid, 256, mma_smem>>>(p_ctxh, p_ctxl, p_outph, p_outpl,
                                          out_proj_b, nullptr, p_lstm, nullptr,
                                          p_combh, p_combl, BT, HH, HH);
    }

    // 9. out = combined @ fc_w^T + fc_b
    {
        dim3 grid(VPAD / 128, MPAD / 128);
        mma_gemm<<<grid, 256, mma_smem>>>(p_combh, p_combl, p_fcwh, p_fcwl,
                                          fc_b, nullptr, nullptr, out, nullptr, nullptr,
                                          BT, VV, HH);
    }
    #undef SPLIT
}

// round 13
// speedup vs baseline: 1.0059x; 1.0059x over previous
#include <cuda_runtime.h>
#include <cuda_bf16.h>
#include <math.h>
#include <stdint.h>
#include <string.h>

// Problem constants
#define BB   32
#define TT   127
#define SS   256
#define HH   512
#define VV   8000
#define NHH  8
#define HDD  64
#define BT   (BB*TT)      // 4064
#define BS   (BB*SS)      // 8192
#define NBLK 128          // persistent LSTM grid (4 groups x 32 blocks)
#define MPAD 4096
#define VPAD 8064

// ---------------- scratch (device globals; no allocations allowed) ----------------
__device__ float g_xg  [BT * 4 * HH];
__device__ float g_lstm[BT * HH];
__device__ float g_q   [BT * HH];
__device__ float g_kv  [BS * 1024];           // packed K(0..511) | V(512..1023)
__device__ unsigned g_flags[NBLK * 2 * 32];

// bf16 hi/lo split buffers (pads stay zero: device globals zero-init, never written)
__device__ __nv_bfloat16 g_embh [MPAD * HH], g_embl [MPAD * HH];
__device__ __nv_bfloat16 g_lstmh[MPAD * HH], g_lstml[MPAD * HH];
__device__ __nv_bfloat16 g_ctxh [MPAD * HH], g_ctxl [MPAD * HH];
__device__ __nv_bfloat16 g_combh[MPAD * HH], g_combl[MPAD * HH];
__device__ __nv_bfloat16 g_ench [BS * HH],   g_encl [BS * HH];
__device__ __nv_bfloat16 g_wihh [4*HH*HH],   g_wihl [4*HH*HH];
__device__ __nv_bfloat16 g_whhh [4*HH*HH],   g_whhl [4*HH*HH];
__device__ __nv_bfloat16 g_inph [3*HH*HH],   g_inpl [3*HH*HH];
__device__ __nv_bfloat16 g_outph[HH*HH],     g_outpl[HH*HH];
__device__ __nv_bfloat16 g_fcwh [VPAD * HH], g_fcwl [VPAD * HH];
// LSTM h ping-pong, bf16 hi/lo, B-operand packed layout
__device__ __nv_bfloat16 g_hbh[2][4 * 4096];
__device__ __nv_bfloat16 g_hbl[2][4 * 4096];

// ---------------- cp.async helpers ----------------
__device__ __forceinline__ void cp_async16(uint32_t dst_smem, const void* src_gmem) {
    asm volatile("cp.async.cg.shared.global [%0], [%1], 16;\n" :: "r"(dst_smem), "l"(src_gmem));
}
__device__ __forceinline__ void cp_async_commit() { asm volatile("cp.async.commit_group;\n"); }
#define CP_WAITN(n) asm volatile("cp.async.wait_group %0;\n" :: "n"(n))

__device__ __forceinline__ uint32_t s2u(const void* p) {
    uint32_t a;
    asm("{ .reg .u64 t; cvta.to.shared.u64 t, %1; cvt.u32.u64 %0, t; }" : "=r"(a) : "l"(p));
    return a;
}
__device__ __forceinline__ void st_bf16_cg(__nv_bfloat16* p, __nv_bfloat16 v) {
    unsigned short u; memcpy(&u, &v, 2);
    asm volatile("st.global.cg.u16 [%0], %1;" :: "l"(p), "h"(u) : "memory");
}
__device__ __forceinline__ void split1(float v, __nv_bfloat16& h, __nv_bfloat16& l) {
    h = __float2bfloat16_rn(v);
    l = __float2bfloat16_rn(v - __bfloat162float(h));
}

// ---------------- mma helpers ----------------
#define LDSM_X4(r0, r1, r2, r3, addr)                                              \
    asm volatile("ldmatrix.sync.aligned.m8n8.x4.shared.b16 {%0,%1,%2,%3}, [%4];"   \
        : "=r"(r0), "=r"(r1), "=r"(r2), "=r"(r3) : "r"(addr))
#define LDSM_X2(r0, r1, addr)                                                      \
    asm volatile("ldmatrix.sync.aligned.m8n8.x2.shared.b16 {%0,%1}, [%2];"         \
        : "=r"(r0), "=r"(r1) : "r"(addr))
#define MMA16816(d, a, b)                                                          \
    asm volatile("mma.sync.aligned.m16n8k16.row.col.f32.bf16.bf16.f32 "            \
        "{%0,%1,%2,%3},{%4,%5,%6,%7},{%8,%9},{%0,%1,%2,%3};"                       \
        : "+f"((d)[0]), "+f"((d)[1]), "+f"((d)[2]), "+f"((d)[3])                   \
        : "r"((a)[0]), "r"((a)[1]), "r"((a)[2]), "r"((a)[3]),                      \
          "r"((b)[0]), "r"((b)[1]))

// ---------------- init: zero h0 (bf16 buffers) and flags ----------------
__global__ void zero_kernel() {
    int i = blockIdx.x * blockDim.x + threadIdx.x;
    if (i < 2 * 4 * 4096) {
        ((__nv_bfloat16*)g_hbh)[i] = __float2bfloat16(0.f);
        ((__nv_bfloat16*)g_hbl)[i] = __float2bfloat16(0.f);
    }
    if (i < NBLK * 2 * 32) g_flags[i] = 0u;
}

// ---------------- embedding gather fused with hi/lo split ----------------
__global__ void gather_split_kernel(const int* __restrict__ targets,
                                    const float* __restrict__ table,
                                    __nv_bfloat16* __restrict__ hi,
                                    __nv_bfloat16* __restrict__ lo) {
    int bt = blockIdx.x;
    int b = bt / TT, t = bt - b * TT;
    int tok = targets[b * 128 + t];
    int j = threadIdx.x;                      // 0..127, 4 floats each
    float4 v = ((const float4*)(table + (size_t)tok * HH))[j];
    __nv_bfloat16 hx, hy, hz, hw, lx, ly, lz, lw;
    split1(v.x, hx, lx); split1(v.y, hy, ly);
    split1(v.z, hz, lz); split1(v.w, hw, lw);
    size_t o = (size_t)bt * HH + j * 4;
    *(__nv_bfloat162*)(hi + o)     = __halves2bfloat162(hx, hy);
    *(__nv_bfloat162*)(hi + o + 2) = __halves2bfloat162(hz, hw);
    *(__nv_bfloat162*)(lo + o)     = __halves2bfloat162(lx, ly);
    *(__nv_bfloat162*)(lo + o + 2) = __halves2bfloat162(lz, lw);
}

// ---------------- fp32 -> bf16 hi/lo split ----------------
__global__ void split_kernel(const float* __restrict__ x,
                             __nv_bfloat16* __restrict__ hi,
                             __nv_bfloat16* __restrict__ lo, int n) {
    int i4 = (blockIdx.x * blockDim.x + threadIdx.x) * 4;
    if (i4 < n) {
        float4 v = *(const float4*)(x + i4);
        __nv_bfloat16 hx, hy, hz, hw, lx, ly, lz, lw;
        split1(v.x, hx, lx); split1(v.y, hy, ly);
        split1(v.z, hz, lz); split1(v.w, hw, lw);
        *(__nv_bfloat162*)(hi + i4)     = __halves2bfloat162(hx, hy);
        *(__nv_bfloat162*)(hi + i4 + 2) = __halves2bfloat162(hz, hw);
        *(__nv_bfloat162*)(lo + i4)     = __halves2bfloat162(lx, ly);
        *(__nv_bfloat162*)(lo + i4 + 2) = __halves2bfloat162(lz, lw);
    }
}

// ---------------- tensor-core GEMM via mma.sync (3xbf16 split) ----------------
// Optional outputs: fp32 C and/or bf16 hi/lo (Chi/Clo) written from the same accumulators.
#define AP   40
#define SEG  (128 * AP * 2)
__global__ __launch_bounds__(256) void mma_gemm(
    const __nv_bfloat16* __restrict__ Ah, const __nv_bfloat16* __restrict__ Al,
    const __nv_bfloat16* __restrict__ Bh, const __nv_bfloat16* __restrict__ Bl,
    const float* __restrict__ bias1, const float* __restrict__ bias2,
    const float* __restrict__ res, float* __restrict__ C,
    __nv_bfloat16* __restrict__ Chi, __nv_bfloat16* __restrict__ Clo,
    int M, int N, int K)
{
    extern __shared__ char smem[];
    const uint32_t sb = s2u(smem);
    const int tid  = threadIdx.x;
    const int wid  = tid >> 5;
    const int lane = tid & 31;
    const int wm = wid >> 2;
    const int wn = wid & 3;
    const int m0 = blockIdx.y * 128;
    const int n0 = blockIdx.x * 128;

    float acc[4][4][4];
    #pragma unroll
    for (int i = 0; i < 4; i++)
        #pragma unroll
        for (int j = 0; j < 4; j++)
            #pragma unroll
            for (int r = 0; r < 4; r++) acc[i][j][r] = 0.f;

    const __nv_bfloat16* srcAh = Ah + (size_t)m0 * K;
    const __nv_bfloat16* srcAl = Al + (size_t)m0 * K;
    const __nv_bfloat16* srcBh = Bh + (size_t)n0 * K;
    const __nv_bfloat16* srcBl = Bl + (size_t)n0 * K;

    auto issue = [&](int k0, int buf) {
        #pragma unroll
        for (int t = 0; t < 8; t++) {
            int idx = tid + t * 256;
            int mat = idx >> 9;
            int r   = (idx >> 2) & 127;
            int j   = idx & 3;
            uint32_t dst = sb + (uint32_t)(mat * 2 + buf) * SEG
                         + (uint32_t)(r * AP + j * 8) * 2;
            const __nv_bfloat16* s =
                (mat == 0 ? srcAh : mat == 1 ? srcAl : mat == 2 ? srcBh : srcBl)
                + (size_t)r * K + k0 + j * 8;
            cp_async16(dst, s);
        }
        cp_async_commit();
    };

    const uint32_t a_off = (uint32_t)(((wm * 64 + (lane & 15)) * AP + (lane >> 4) * 8) * 2);
    const uint32_t b_off = (uint32_t)(((wn * 32 + (lane & 7)) * AP + ((lane >> 3) & 1) * 8) * 2);

    const int NC = K / 32;
    issue(0, 0);
    #pragma unroll 1
    for (int c = 0; c < NC; c++) {
        const int buf = c & 1;
        if (c + 1 < NC) { issue((c + 1) * 32, buf ^ 1); CP_WAITN(1); }
        else           { CP_WAITN(0); }
        __syncthreads();

        #pragma unroll
        for (int ks = 0; ks < 2; ks++) {
            const uint32_t kb = (uint32_t)(ks * 32);
            uint32_t bh[4][2], bl[4][2];
            #pragma unroll
            for (int nt = 0; nt < 4; nt++) {
                uint32_t ba = sb + (uint32_t)(4 + buf) * SEG + b_off
                            + (uint32_t)(nt * 8 * AP * 2) + kb;
                LDSM_X2(bh[nt][0], bh[nt][1], ba);
                LDSM_X2(bl[nt][0], bl[nt][1], ba + 2u * SEG);
            }
            #pragma unroll
            for (int mt = 0; mt < 4; mt++) {
                uint32_t ah[4], al[4];
                uint32_t aa = sb + (uint32_t)buf * SEG + a_off
                            + (uint32_t)(mt * 16 * AP * 2) + kb;
                LDSM_X4(ah[0], ah[1], ah[2], ah[3], aa);
                LDSM_X4(al[0], al[1], al[2], al[3], aa + 2u * SEG);
                #pragma unroll
                for (int nt = 0; nt < 4; nt++) {
                    MMA16816(acc[mt][nt], ah, bh[nt]);
                    MMA16816(acc[mt][nt], ah, bl[nt]);
                    MMA16816(acc[mt][nt], al, bh[nt]);
                }
            }
        }
        __syncthreads();
    }

    const int tm = lane >> 2;
    const int tc = (lane & 3) * 2;
    #pragma unroll
    for (int mt = 0; mt < 4; mt++) {
        #pragma unroll
        for (int nt = 0; nt < 4; nt++) {
            int col = n0 + wn * 32 + nt * 8 + tc;
            if (col + 2 > N) continue;           // all N are multiples of 128 here
            float2 v0 = make_float2(acc[mt][nt][0], acc[mt][nt][1]);
            float2 v1 = make_float2(acc[mt][nt][2], acc[mt][nt][3]);
            if (bias1) {
                float2 b = *(const float2*)(bias1 + col);
                v0.x += b.x; v0.y += b.y; v1.x += b.x; v1.y += b.y;
            }
            if (bias2) {
                float2 b = *(const float2*)(bias2 + col);
                v0.x += b.x; v0.y += b.y; v1.x += b.x; v1.y += b.y;
            }
            #pragma unroll
            for (int half = 0; half < 2; half++) {
                int row = m0 + wm * 64 + mt * 16 + tm + half * 8;
                if (row >= M) continue;
                float2 o = half ? v1 : v0;
                if (res) {
                    float2 rr = *(const float2*)(res + (size_t)row * N + col);
                    o.x += rr.x; o.y += rr.y;
                }
                if (C) *(float2*)(C + (size_t)row * N + col) = o;
                if (Chi) {
                    __nv_bfloat16 h0, h1, l0, l1;
                    split1(o.x, h0, l0); split1(o.y, h1, l1);
                    *(__nv_bfloat162*)(Chi + (size_t)row * N + col) = __halves2bfloat162(h0, h1);
                    *(__nv_bfloat162*)(Clo + (size_t)row * N + col) = __halves2bfloat162(l0, l1);
                }
            }
        }
    }
}

// ---------------- tensor-core persistent LSTM (exact R11 version: lean step loop) ----------------
#define LW_SEG  (64 * AP * 2)
#define LH_SEG  (8 * AP * 2)
#define SM_WH   0
#define SM_WL   81920
#define SM_HH   163840
#define SM_HL   174080
#define SM_RED  184320
#define LSTM_SMEM (SM_RED + 16 * 513 * 4)

__global__ __launch_bounds__(512) void lstm_mma_kernel(
    const float* __restrict__ xg,
    const __nv_bfloat16* __restrict__ whh_h, const __nv_bfloat16* __restrict__ whh_l,
    float* __restrict__ lstm_out)
{
    extern __shared__ char smem[];
    const uint32_t sb = s2u(smem);
    float* red = (float*)(smem + SM_RED);

    const int tid   = threadIdx.x;
    const int wid   = tid >> 5;
    const int lane  = tid & 31;
    const int group = blockIdx.x >> 5;
    const int gslot = blockIdx.x & 31;
    const int col_base = gslot * 16;

    for (int it = tid; it < 16 * 64 * 4; it += 512) {
        int s = it >> 8;
        int r = (it >> 2) & 63;
        int j = it & 3;
        int gate = r >> 4, colL = r & 15;
        size_t src = (size_t)(gate * HH + col_base + colL) * HH + s * 32 + j * 8;
        uint32_t dst = (uint32_t)(s * LW_SEG + r * (AP * 2) + j * 16);
        cp_async16(sb + SM_WH + dst, whh_h + src);
        cp_async16(sb + SM_WL + dst, whh_l + src);
    }
    cp_async_commit();
    CP_WAITN(0);
    __syncthreads();

    const int seg = wid;
    const uint32_t a_off = (uint32_t)(((lane & 15) * AP + (lane >> 4) * 8) * 2);
    uint32_t Afh[4][2][4], Afl[4][2][4];
    #pragma unroll
    for (int g = 0; g < 4; g++) {
        #pragma unroll
        for (int ks = 0; ks < 2; ks++) {
            uint32_t aa = sb + (uint32_t)(seg * LW_SEG + g * 16 * AP * 2) + a_off
                        + (uint32_t)(ks * 32);
            LDSM_X4(Afh[g][ks][0], Afh[g][ks][1], Afh[g][ks][2], Afh[g][ks][3], aa);
            LDSM_X4(Afl[g][ks][0], Afl[g][ks][1], Afl[g][ks][2], Afl[g][ks][3],
                    aa + (uint32_t)(SM_WL - SM_WH));
        }
    }

    const uint32_t b_off = (uint32_t)(((lane & 7) * AP + ((lane >> 3) & 1) * 8) * 2);

    const int acolL = tid >> 3;
    const int ab    = tid & 7;
    const int gcol  = col_base + acolL;
    const int abatch = group * 8 + ab;
    const int hseg  = gcol >> 5;
    const int hc32  = gcol & 31;
    const size_t xgb = (size_t)(abatch * TT) * (4 * HH) + gcol;
    unsigned* my_flag = &g_flags[blockIdx.x * 64];
    float c_reg = 0.f;

    const __nv_bfloat16* hbh_rd[2] = { g_hbh[0] + group * 4096, g_hbh[1] + group * 4096 };
    const __nv_bfloat16* hbl_rd[2] = { g_hbl[0] + group * 4096, g_hbl[1] + group * 4096 };
    __nv_bfloat16* hbh_wr[2] = { g_hbh[0] + group * 4096, g_hbh[1] + group * 4096 };
    __nv_bfloat16* hbl_wr[2] = { g_hbl[0] + group * 4096, g_hbl[1] + group * 4096 };

    for (int t = 0; t < TT; t++) {
        const int rb = t & 1;
        const int wb = rb ^ 1;

        if (t > 0) {
            if (tid < 32) {
                const unsigned* fp = &g_flags[(group * 32 + tid) * 64];
                unsigned v;
                do {
                    asm volatile("ld.acquire.gpu.global.u32 %0, [%1];"
                                 : "=r"(v) : "l"(fp) : "memory");
                } while (v < (unsigned)t);
            }
            __syncthreads();
        }

        #pragma unroll
        for (int i = 0; i < 2; i++) {
            int it = tid + i * 512;
            int m  = it >> 9;
            int idx = it & 511;
            int s = idx >> 5, b = (idx >> 2) & 7, j = idx & 3;
            const __nv_bfloat16* src = (m ? hbl_rd[rb] : hbh_rd[rb])
                                     + s * 256 + b * 32 + j * 8;
            uint32_t dst = sb + (uint32_t)(m ? SM_HL : SM_HH)
                         + (uint32_t)(s * LH_SEG + b * (AP * 2) + j * 16);
            cp_async16(dst, src);
        }
        cp_async_commit();

        float xv0 = 0.f, xv1 = 0.f, xv2 = 0.f, xv3 = 0.f;
        if (tid < 128) {
            const float* xp = xg + xgb + (size_t)t * (4 * HH);
            xv0 = __ldg(xp);
            xv1 = __ldg(xp + HH);
            xv2 = __ldg(xp + 2 * HH);
            xv3 = __ldg(xp + 3 * HH);
        }

        CP_WAITN(0);
        __syncthreads();

        float acc[4][4];
        #pragma unroll
        for (int g = 0; g < 4; g++)
            #pragma unroll
            for (int r = 0; r < 4; r++) acc[g][r] = 0.f;

        #pragma unroll
        for (int ks = 0; ks < 2; ks++) {
            uint32_t ba = sb + SM_HH + (uint32_t)(seg * LH_SEG) + b_off + (uint32_t)(ks * 32);
            uint32_t bh[2], bl[2];
            LDSM_X2(bh[0], bh[1], ba);
            LDSM_X2(bl[0], bl[1], ba + (uint32_t)(SM_HL - SM_HH));
            #pragma unroll
            for (int g = 0; g < 4; g++) {
                MMA16816(acc[g], Afh[g][ks], bh);
                MMA16816(acc[g], Afh[g][ks], bl);
                MMA16816(acc[g], Afl[g][ks], bh);
            }
        }

        {
            const int tm = lane >> 2;
            const int tc = (lane & 3) * 2;
            float* rp = red + wid * 513;
            #pragma unroll
            for (int g = 0; g < 4; g++) {
                rp[g * 128 + tm * 8 + tc]           = acc[g][0];
                rp[g * 128 + tm * 8 + tc + 1]       = acc[g][1];
                rp[g * 128 + (tm + 8) * 8 + tc]     = acc[g][2];
                rp[g * 128 + (tm + 8) * 8 + tc + 1] = acc[g][3];
            }
        }
        __syncthreads();

        if (tid < 128) {
            const int p = acolL * 8 + ab;
            float gv[4] = { xv0, xv1, xv2, xv3 };
            #pragma unroll
            for (int w = 0; w < 16; w++) {
                const float* rp = red + w * 513 + p;
                gv[0] += rp[0];
                gv[1] += rp[128];
                gv[2] += rp[256];
                gv[3] += rp[384];
            }
            float ig = 1.f / (1.f + __expf(-gv[0]));
            float fg = 1.f / (1.f + __expf(-gv[1]));
            float gg = tanhf(gv[2]);
            float og = 1.f / (1.f + __expf(-gv[3]));
            c_reg = fg * c_reg + ig * gg;
            float hn = og * tanhf(c_reg);
            lstm_out[(size_t)(abatch * TT + t) * HH + gcol] = hn;
            __nv_bfloat16 hh_, hl_;
            split1(hn, hh_, hl_);
            int off = hseg * 256 + ab * 32 + hc32;
            st_bf16_cg(hbh_wr[wb] + off, hh_);
            st_bf16_cg(hbl_wr[wb] + off, hl_);
        }
        __syncthreads();

        if (tid == 0) {
            asm volatile("fence.acq_rel.gpu;" ::: "memory");
            asm volatile("st.release.gpu.global.u32 [%0], %1;"
                         :: "l"(my_flag), "r"((unsigned)(t + 1)) : "memory");
        }
    }
}

// ---------------- fused attention (packed kv input, bf16 hi/lo ctx output) ----------------
#define KTP 257
#define QSP 68
#define PSP 260
__global__ __launch_bounds__(256) void attn_kernel(
    const float* __restrict__ q, const float* __restrict__ kv,
    __nv_bfloat16* __restrict__ ctxh, __nv_bfloat16* __restrict__ ctxl)
{
    extern __shared__ float smemf[];
    float* Kt   = smemf;
    float* Vt   = Kt + 64 * KTP;
    float* qs   = Vt + 64 * KTP;
    float* ps   = qs + 32 * QSP;
    float* sums = ps + 32 * PSP;

    const int t0 = blockIdx.x * 32;
    const int h  = blockIdx.y;
    const int b  = blockIdx.z;
    const int tid = threadIdx.x;

    for (int idx = tid; idx < 256 * 16; idx += 256) {
        int s = idx >> 4; int d4 = (idx & 15) << 2;
        size_t off = (size_t)(b * SS + s) * 1024 + h * HDD + d4;
        float4 kvv = *(const float4*)(kv + off);
        Kt[(d4 + 0) * KTP + s] = kvv.x; Kt[(d4 + 1) * KTP + s] = kvv.y;
        Kt[(d4 + 2) * KTP + s] = kvv.z; Kt[(d4 + 3) * KTP + s] = kvv.w;
        float4 vvv = *(const float4*)(kv + off + 512);
        Vt[(d4 + 0) * KTP + s] = vvv.x; Vt[(d4 + 1) * KTP + s] = vvv.y;
        Vt[(d4 + 2) * KTP + s] = vvv.z; Vt[(d4 + 3) * KTP + s] = vvv.w;
    }
    for (int idx = tid; idx < 32 * 16; idx += 256) {
        int r = idx >> 4; int d4 = (idx & 15) << 2;
        int trow = t0 + r;
        float4 qv = make_float4(0.f, 0.f, 0.f, 0.f);
        if (trow < TT)
            qv = *(const float4*)(q + (size_t)(b * TT + trow) * HH + h * HDD + d4);
        float* d = qs + r * QSP + d4;
        d[0] = qv.x; d[1] = qv.y; d[2] = qv.z; d[3] = qv.w;
    }
    __syncthreads();

    const int r  = tid >> 3;
    const int lc = tid & 7;

    float qreg[64];
    #pragma unroll
    for (int d = 0; d < 64; d++) qreg[d] = qs[r * QSP + d];

    float sc[32];
    for (int si = 0; si < 32; si++) {
        int s = si * 8 + lc;
        float acc = 0.f;
        #pragma unroll
        for (int d = 0; d < 64; d++) acc += qreg[d] * Kt[d * KTP + s];
        sc[si] = acc * 0.125f;
    }
    float m = -1e30f;
    #pragma unroll
    for (int si = 0; si < 32; si++) m = fmaxf(m, sc[si]);
    m = fmaxf(m, __shfl_xor_sync(0xffffffff, m, 1));
    m = fmaxf(m, __shfl_xor_sync(0xffffffff, m, 2));
    m = fmaxf(m, __shfl_xor_sync(0xffffffff, m, 4));
    float ssum = 0.f;
    #pragma unroll
    for (int si = 0; si < 32; si++) {
        float e = __expf(sc[si] - m);
        ssum += e;
        ps[r * PSP + si * 8 + lc] = e;
    }
    ssum += __shfl_xor_sync(0xffffffff, ssum, 1);
    ssum += __shfl_xor_sync(0xffffffff, ssum, 2);
    ssum += __shfl_xor_sync(0xffffffff, ssum, 4);
    if (lc == 0) sums[r] = ssum;
    __syncthreads();

    float accv[8];
    #pragma unroll
    for (int j = 0; j < 8; j++) accv[j] = 0.f;
    const float* prow = ps + r * PSP;
    #pragma unroll 4
    for (int s = 0; s < 256; s++) {
        float pv = prow[s];
        #pragma unroll
        for (int j = 0; j < 8; j++)
            accv[j] += pv * Vt[(lc + 8 * j) * KTP + s];
    }
    float inv = 1.0f / sums[r];
    int trow = t0 + r;
    if (trow < TT) {
        size_t base = (size_t)(b * TT + trow) * HH + h * HDD;
        #pragma unroll
        for (int j = 0; j < 8; j++) {
            float val = accv[j] * inv;
            __nv_bfloat16 hv, lv;
            split1(val, hv, lv);
            ctxh[base + lc + 8 * j] = hv;
            ctxl[base + lc + 8 * j] = lv;
        }
    }
}

// ---------------- launch ----------------
extern "C" void kernel_launch(void* const* d_in, const int* in_sizes, int n_in,
                              void* d_out, int out_size) {
    const int*   targets  = (const int*)  d_in[0];
    const float* enc      = (const float*)d_in[1];
    const float* embedding= (const float*)d_in[2];
    const float* w_ih     = (const float*)d_in[3];
    const float* w_hh     = (const float*)d_in[4];
    const float* b_ih     = (const float*)d_in[5];
    const float* b_hh     = (const float*)d_in[6];
    const float* in_proj_w= (const float*)d_in[7];
    const float* in_proj_b= (const float*)d_in[8];
    const float* out_proj_w=(const float*)d_in[9];
    const float* out_proj_b=(const float*)d_in[10];
    const float* fc_w     = (const float*)d_in[11];
    const float* fc_b     = (const float*)d_in[12];
    float* out = (float*)d_out;

    float *p_xg, *p_lstm, *p_q, *p_kv;
    cudaGetSymbolAddress((void**)&p_xg,   g_xg);
    cudaGetSymbolAddress((void**)&p_lstm, g_lstm);
    cudaGetSymbolAddress((void**)&p_q,    g_q);
    cudaGetSymbolAddress((void**)&p_kv,   g_kv);
    __nv_bfloat16 *p_embh, *p_embl, *p_lstmh, *p_lstml, *p_ctxh, *p_ctxl,
                  *p_combh, *p_combl, *p_ench, *p_encl, *p_wihh, *p_wihl,
                  *p_whhh, *p_whhl, *p_inph, *p_inpl, *p_outph, *p_outpl,
                  *p_fcwh, *p_fcwl;
    cudaGetSymbolAddress((void**)&p_embh,  g_embh);
    cudaGetSymbolAddress((void**)&p_embl,  g_embl);
    cudaGetSymbolAddress((void**)&p_lstmh, g_lstmh);
    cudaGetSymbolAddress((void**)&p_lstml, g_lstml);
    cudaGetSymbolAddress((void**)&p_ctxh,  g_ctxh);
    cudaGetSymbolAddress((void**)&p_ctxl,  g_ctxl);
    cudaGetSymbolAddress((void**)&p_combh, g_combh);
    cudaGetSymbolAddress((void**)&p_combl, g_combl);
    cudaGetSymbolAddress((void**)&p_ench,  g_ench);
    cudaGetSymbolAddress((void**)&p_encl,  g_encl);
    cudaGetSymbolAddress((void**)&p_wihh,  g_wihh);
    cudaGetSymbolAddress((void**)&p_wihl,  g_wihl);
    cudaGetSymbolAddress((void**)&p_whhh,  g_whhh);
    cudaGetSymbolAddress((void**)&p_whhl,  g_whhl);
    cudaGetSymbolAddress((void**)&p_inph,  g_inph);
    cudaGetSymbolAddress((void**)&p_inpl,  g_inpl);
    cudaGetSymbolAddress((void**)&p_outph, g_outph);
    cudaGetSymbolAddress((void**)&p_outpl, g_outpl);
    cudaGetSymbolAddress((void**)&p_fcwh,  g_fcwh);
    cudaGetSymbolAddress((void**)&p_fcwl,  g_fcwl);

    const int attn_smem = (64 * KTP * 2 + 32 * QSP + 32 * PSP + 32) * (int)sizeof(float);
    const int mma_smem  = 8 * SEG;
    cudaFuncSetAttribute(attn_kernel,     cudaFuncAttributeMaxDynamicSharedMemorySize, attn_smem);
    cudaFuncSetAttribute(mma_gemm,        cudaFuncAttributeMaxDynamicSharedMemorySize, mma_smem);
    cudaFuncSetAttribute(lstm_mma_kernel, cudaFuncAttributeMaxDynamicSharedMemorySize, LSTM_SMEM);

    #define SPLIT(src, hi, lo, n) split_kernel<<<((n)/4 + 255) / 256, 256>>>(src, hi, lo, n)

    // 1. zero h0 + flags
    zero_kernel<<<(2 * 4 * 4096 + 255) / 256, 256>>>();

    // 2. weight/input splits
    SPLIT(w_ih,       p_wihh,  p_wihl,  4 * HH * HH);
    SPLIT(w_hh,       p_whhh,  p_whhl,  4 * HH * HH);
    SPLIT(in_proj_w,  p_inph,  p_inpl,  3 * HH * HH);
    SPLIT(out_proj_w, p_outph, p_outpl, HH * HH);
    SPLIT(fc_w,       p_fcwh,  p_fcwl,  VV * HH);
    SPLIT(enc,        p_ench,  p_encl,  BS * HH);

    // 3. gather embeddings (fused split)
    gather_split_kernel<<<BT, 128>>>(targets, embedding, p_embh, p_embl);

    // 4. xg = emb @ w_ih^T + b_ih + b_hh
    {
        dim3 grid(4 * HH / 128, MPAD / 128);
        mma_gemm<<<grid, 256, mma_smem>>>(p_embh, p_embl, p_wihh, p_wihl,
                                          b_ih, b_hh, nullptr, p_xg, nullptr, nullptr,
                                          BT, 4 * HH, HH);
    }

    // 5. LSTM recurrence (lean step loop; split done once afterwards)
    lstm_mma_kernel<<<NBLK, 512, LSTM_SMEM>>>(p_xg, p_whhh, p_whhl, p_lstm);
    SPLIT(p_lstm, p_lstmh, p_lstml, BT * HH);

    // 6. q projection + merged K|V projection
    {
        dim3 gq(HH / 128, MPAD / 128);
        mma_gemm<<<gq, 256, mma_smem>>>(p_lstmh, p_lstml, p_inph, p_inpl,
                                        in_proj_b, nullptr, nullptr, p_q, nullptr, nullptr,
                                        BT, HH, HH);
        dim3 gkv(1024 / 128, BS / 128);
        mma_gemm<<<gkv, 256, mma_smem>>>(p_ench, p_encl, p_inph + (size_t)HH * HH,
                                         p_inpl + (size_t)HH * HH,
                                         in_proj_b + HH, nullptr, nullptr, p_kv,
                                         nullptr, nullptr, BS, 1024, HH);
    }

    // 7. fused attention -> ctx hi/lo (split fused; throughput path, not recurrence)
    {
        dim3 grid(4, NHH, BB);
        attn_kernel<<<grid, 256, attn_smem>>>(p_q, p_kv, p_ctxh, p_ctxl);
    }

    // 8. combined = ctx @ out_proj^T + out_proj_b + lstm_out  (direct bf16 hi/lo output)
    {
        dim3 grid(HH / 128, MPAD / 128);
        mma_gemm<<<grid, 256, mma_smem>>>(p_ctxh, p_ctxl, p_outph, p_outpl,
                                          out_proj_b, nullptr, p_lstm, nullptr,
                                          p_combh, p_combl, BT, HH, HH);
    }

    // 9. out = combined @ fc_w^T + fc_b
    {
        dim3 grid(VPAD / 128, MPAD / 128);
        mma_gemm<<<grid, 256, mma_smem>>>(p_combh, p_combl, p_fcwh, p_fcwl,
                                          fc_b, nullptr, nullptr, out, nullptr, nullptr,
                                          BT, VV, HH);
    }
    #undef SPLIT
}

// round 14
// speedup vs baseline: 1.0327x; 1.0266x over previous
#include <cuda_runtime.h>
#include <cuda_bf16.h>
#include <math.h>
#include <stdint.h>
#include <string.h>

// Problem constants
#define BB   32
#define TT   127
#define SS   256
#define HH   512
#define VV   8000
#define NHH  8
#define HDD  64
#define BT   (BB*TT)      // 4064
#define BS   (BB*SS)      // 8192
#define NBLK 128          // persistent LSTM grid (4 groups x 32 blocks)
#define MPAD 4096
#define VPAD 8064

// ---------------- scratch (device globals; no allocations allowed) ----------------
__device__ float g_xg  [BT * 4 * HH];
__device__ float g_lstm[BT * HH];
__device__ float g_q   [BT * HH];
__device__ float g_kv  [BS * 1024];           // packed K(0..511) | V(512..1023)
__device__ unsigned g_flags[NBLK * 2 * 32];

// bf16 hi/lo split buffers (pads stay zero: device globals zero-init, never written)
__device__ __nv_bfloat16 g_embh [MPAD * HH], g_embl [MPAD * HH];
__device__ __nv_bfloat16 g_lstmh[MPAD * HH], g_lstml[MPAD * HH];
__device__ __nv_bfloat16 g_ctxh [MPAD * HH], g_ctxl [MPAD * HH];
__device__ __nv_bfloat16 g_combh[MPAD * HH], g_combl[MPAD * HH];
__device__ __nv_bfloat16 g_ench [BS * HH],   g_encl [BS * HH];
__device__ __nv_bfloat16 g_wihh [4*HH*HH],   g_wihl [4*HH*HH];
__device__ __nv_bfloat16 g_whhh [4*HH*HH],   g_whhl [4*HH*HH];
__device__ __nv_bfloat16 g_inph [3*HH*HH],   g_inpl [3*HH*HH];
__device__ __nv_bfloat16 g_outph[HH*HH],     g_outpl[HH*HH];
__device__ __nv_bfloat16 g_fcwh [VPAD * HH], g_fcwl [VPAD * HH];
// LSTM h ping-pong, bf16 hi/lo, B-operand packed layout
__device__ __nv_bfloat16 g_hbh[2][4 * 4096];
__device__ __nv_bfloat16 g_hbl[2][4 * 4096];

// ---------------- cp.async helpers ----------------
__device__ __forceinline__ void cp_async16(uint32_t dst_smem, const void* src_gmem) {
    asm volatile("cp.async.cg.shared.global [%0], [%1], 16;\n" :: "r"(dst_smem), "l"(src_gmem));
}
__device__ __forceinline__ void cp_async_commit() { asm volatile("cp.async.commit_group;\n"); }
#define CP_WAITN(n) asm volatile("cp.async.wait_group %0;\n" :: "n"(n))

__device__ __forceinline__ uint32_t s2u(const void* p) {
    uint32_t a;
    asm("{ .reg .u64 t; cvta.to.shared.u64 t, %1; cvt.u32.u64 %0, t; }" : "=r"(a) : "l"(p));
    return a;
}
__device__ __forceinline__ void st_bf16_cg(__nv_bfloat16* p, __nv_bfloat16 v) {
    unsigned short u; memcpy(&u, &v, 2);
    asm volatile("st.global.cg.u16 [%0], %1;" :: "l"(p), "h"(u) : "memory");
}
__device__ __forceinline__ void split1(float v, __nv_bfloat16& h, __nv_bfloat16& l) {
    h = __float2bfloat16_rn(v);
    l = __float2bfloat16_rn(v - __bfloat162float(h));
}

// ---------------- mma helpers ----------------
#define LDSM_X4(r0, r1, r2, r3, addr)                                              \
    asm volatile("ldmatrix.sync.aligned.m8n8.x4.shared.b16 {%0,%1,%2,%3}, [%4];"   \
        : "=r"(r0), "=r"(r1), "=r"(r2), "=r"(r3) : "r"(addr))
#define LDSM_X2(r0, r1, addr)                                                      \
    asm volatile("ldmatrix.sync.aligned.m8n8.x2.shared.b16 {%0,%1}, [%2];"         \
        : "=r"(r0), "=r"(r1) : "r"(addr))
#define MMA16816(d, a, b)                                                          \
    asm volatile("mma.sync.aligned.m16n8k16.row.col.f32.bf16.bf16.f32 "            \
        "{%0,%1,%2,%3},{%4,%5,%6,%7},{%8,%9},{%0,%1,%2,%3};"                       \
        : "+f"((d)[0]), "+f"((d)[1]), "+f"((d)[2]), "+f"((d)[3])                   \
        : "r"((a)[0]), "r"((a)[1]), "r"((a)[2]), "r"((a)[3]),                      \
          "r"((b)[0]), "r"((b)[1]))

// ---------------- init: zero h0 (bf16 buffers) and flags ----------------
__global__ void zero_kernel() {
    int i = blockIdx.x * blockDim.x + threadIdx.x;
    if (i < 2 * 4 * 4096) {
        ((__nv_bfloat16*)g_hbh)[i] = __float2bfloat16(0.f);
        ((__nv_bfloat16*)g_hbl)[i] = __float2bfloat16(0.f);
    }
    if (i < NBLK * 2 * 32) g_flags[i] = 0u;
}

// ---------------- embedding gather fused with hi/lo split ----------------
__global__ void gather_split_kernel(const int* __restrict__ targets,
                                    const float* __restrict__ table,
                                    __nv_bfloat16* __restrict__ hi,
                                    __nv_bfloat16* __restrict__ lo) {
    int bt = blockIdx.x;
    int b = bt / TT, t = bt - b * TT;
    int tok = targets[b * 128 + t];
    int j = threadIdx.x;                      // 0..127, 4 floats each
    float4 v = ((const float4*)(table + (size_t)tok * HH))[j];
    __nv_bfloat16 hx, hy, hz, hw, lx, ly, lz, lw;
    split1(v.x, hx, lx); split1(v.y, hy, ly);
    split1(v.z, hz, lz); split1(v.w, hw, lw);
    size_t o = (size_t)bt * HH + j * 4;
    *(__nv_bfloat162*)(hi + o)     = __halves2bfloat162(hx, hy);
    *(__nv_bfloat162*)(hi + o + 2) = __halves2bfloat162(hz, hw);
    *(__nv_bfloat162*)(lo + o)     = __halves2bfloat162(lx, ly);
    *(__nv_bfloat162*)(lo + o + 2) = __halves2bfloat162(lz, lw);
}

// ---------------- fp32 -> bf16 hi/lo split ----------------
__global__ void split_kernel(const float* __restrict__ x,
                             __nv_bfloat16* __restrict__ hi,
                             __nv_bfloat16* __restrict__ lo, int n) {
    int i4 = (blockIdx.x * blockDim.x + threadIdx.x) * 4;
    if (i4 < n) {
        float4 v = *(const float4*)(x + i4);
        __nv_bfloat16 hx, hy, hz, hw, lx, ly, lz, lw;
        split1(v.x, hx, lx); split1(v.y, hy, ly);
        split1(v.z, hz, lz); split1(v.w, hw, lw);
        *(__nv_bfloat162*)(hi + i4)     = __halves2bfloat162(hx, hy);
        *(__nv_bfloat162*)(hi + i4 + 2) = __halves2bfloat162(hz, hw);
        *(__nv_bfloat162*)(lo + i4)     = __halves2bfloat162(lx, ly);
        *(__nv_bfloat162*)(lo + i4 + 2) = __halves2bfloat162(lz, lw);
    }
}

// ---------------- tensor-core GEMM via mma.sync (3xbf16 split) ----------------
// __launch_bounds__(256, 2): cap registers at 128 so two blocks co-reside per SM
// (the bf16 epilogue path must not cost mainloop occupancy).
#define AP   40
#define SEG  (128 * AP * 2)
__global__ __launch_bounds__(256, 2) void mma_gemm(
    const __nv_bfloat16* __restrict__ Ah, const __nv_bfloat16* __restrict__ Al,
    const __nv_bfloat16* __restrict__ Bh, const __nv_bfloat16* __restrict__ Bl,
    const float* __restrict__ bias1, const float* __restrict__ bias2,
    const float* __restrict__ res, float* __restrict__ C,
    __nv_bfloat16* __restrict__ Chi, __nv_bfloat16* __restrict__ Clo,
    int M, int N, int K)
{
    extern __shared__ char smem[];
    const uint32_t sb = s2u(smem);
    const int tid  = threadIdx.x;
    const int wid  = tid >> 5;
    const int lane = tid & 31;
    const int wm = wid >> 2;
    const int wn = wid & 3;
    const int m0 = blockIdx.y * 128;
    const int n0 = blockIdx.x * 128;

    float acc[4][4][4];
    #pragma unroll
    for (int i = 0; i < 4; i++)
        #pragma unroll
        for (int j = 0; j < 4; j++)
            #pragma unroll
            for (int r = 0; r < 4; r++) acc[i][j][r] = 0.f;

    const __nv_bfloat16* srcAh = Ah + (size_t)m0 * K;
    const __nv_bfloat16* srcAl = Al + (size_t)m0 * K;
    const __nv_bfloat16* srcBh = Bh + (size_t)n0 * K;
    const __nv_bfloat16* srcBl = Bl + (size_t)n0 * K;

    auto issue = [&](int k0, int buf) {
        #pragma unroll
        for (int t = 0; t < 8; t++) {
            int idx = tid + t * 256;
            int mat = idx >> 9;
            int r   = (idx >> 2) & 127;
            int j   = idx & 3;
            uint32_t dst = sb + (uint32_t)(mat * 2 + buf) * SEG
                         + (uint32_t)(r * AP + j * 8) * 2;
            const __nv_bfloat16* s =
                (mat == 0 ? srcAh : mat == 1 ? srcAl : mat == 2 ? srcBh : srcBl)
                + (size_t)r * K + k0 + j * 8;
            cp_async16(dst, s);
        }
        cp_async_commit();
    };

    const uint32_t a_off = (uint32_t)(((wm * 64 + (lane & 15)) * AP + (lane >> 4) * 8) * 2);
    const uint32_t b_off = (uint32_t)(((wn * 32 + (lane & 7)) * AP + ((lane >> 3) & 1) * 8) * 2);

    const int NC = K / 32;
    issue(0, 0);
    #pragma unroll 1
    for (int c = 0; c < NC; c++) {
        const int buf = c & 1;
        if (c + 1 < NC) { issue((c + 1) * 32, buf ^ 1); CP_WAITN(1); }
        else           { CP_WAITN(0); }
        __syncthreads();

        #pragma unroll
        for (int ks = 0; ks < 2; ks++) {
            const uint32_t kb = (uint32_t)(ks * 32);
            uint32_t bh[4][2], bl[4][2];
            #pragma unroll
            for (int nt = 0; nt < 4; nt++) {
                uint32_t ba = sb + (uint32_t)(4 + buf) * SEG + b_off
                            + (uint32_t)(nt * 8 * AP * 2) + kb;
                LDSM_X2(bh[nt][0], bh[nt][1], ba);
                LDSM_X2(bl[nt][0], bl[nt][1], ba + 2u * SEG);
            }
            #pragma unroll
            for (int mt = 0; mt < 4; mt++) {
                uint32_t ah[4], al[4];
                uint32_t aa = sb + (uint32_t)buf * SEG + a_off
                            + (uint32_t)(mt * 16 * AP * 2) + kb;
                LDSM_X4(ah[0], ah[1], ah[2], ah[3], aa);
                LDSM_X4(al[0], al[1], al[2], al[3], aa + 2u * SEG);
                #pragma unroll
                for (int nt = 0; nt < 4; nt++) {
                    MMA16816(acc[mt][nt], ah, bh[nt]);
                    MMA16816(acc[mt][nt], ah, bl[nt]);
                    MMA16816(acc[mt][nt], al, bh[nt]);
                }
            }
        }
        __syncthreads();
    }

    const int tm = lane >> 2;
    const int tc = (lane & 3) * 2;
    #pragma unroll
    for (int mt = 0; mt < 4; mt++) {
        #pragma unroll
        for (int nt = 0; nt < 4; nt++) {
            int col = n0 + wn * 32 + nt * 8 + tc;
            if (col + 2 > N) continue;           // all N are multiples of 128 here
            float2 v0 = make_float2(acc[mt][nt][0], acc[mt][nt][1]);
            float2 v1 = make_float2(acc[mt][nt][2], acc[mt][nt][3]);
            if (bias1) {
                float2 b = *(const float2*)(bias1 + col);
                v0.x += b.x; v0.y += b.y; v1.x += b.x; v1.y += b.y;
            }
            if (bias2) {
                float2 b = *(const float2*)(bias2 + col);
                v0.x += b.x; v0.y += b.y; v1.x += b.x; v1.y += b.y;
            }
            #pragma unroll
            for (int half = 0; half < 2; half++) {
                int row = m0 + wm * 64 + mt * 16 + tm + half * 8;
                if (row >= M) continue;
                float2 o = half ? v1 : v0;
                if (res) {
                    float2 rr = *(const float2*)(res + (size_t)row * N + col);
                    o.x += rr.x; o.y += rr.y;
                }
                if (C) *(float2*)(C + (size_t)row * N + col) = o;
                if (Chi) {
                    __nv_bfloat16 h0, h1, l0, l1;
                    split1(o.x, h0, l0); split1(o.y, h1, l1);
                    *(__nv_bfloat162*)(Chi + (size_t)row * N + col) = __halves2bfloat162(h0, h1);
                    *(__nv_bfloat162*)(Clo + (size_t)row * N + col) = __halves2bfloat162(l0, l1);
                }
            }
        }
    }
}

// ---------------- tensor-core persistent LSTM (lean step loop) ----------------
#define LW_SEG  (64 * AP * 2)
#define LH_SEG  (8 * AP * 2)
#define SM_WH   0
#define SM_WL   81920
#define SM_HH   163840
#define SM_HL   174080
#define SM_RED  184320
#define LSTM_SMEM (SM_RED + 16 * 513 * 4)

__global__ __launch_bounds__(512) void lstm_mma_kernel(
    const float* __restrict__ xg,
    const __nv_bfloat16* __restrict__ whh_h, const __nv_bfloat16* __restrict__ whh_l,
    float* __restrict__ lstm_out)
{
    extern __shared__ char smem[];
    const uint32_t sb = s2u(smem);
    float* red = (float*)(smem + SM_RED);

    const int tid   = threadIdx.x;
    const int wid   = tid >> 5;
    const int lane  = tid & 31;
    const int group = blockIdx.x >> 5;
    const int gslot = blockIdx.x & 31;
    const int col_base = gslot * 16;

    for (int it = tid; it < 16 * 64 * 4; it += 512) {
        int s = it >> 8;
        int r = (it >> 2) & 63;
        int j = it & 3;
        int gate = r >> 4, colL = r & 15;
        size_t src = (size_t)(gate * HH + col_base + colL) * HH + s * 32 + j * 8;
        uint32_t dst = (uint32_t)(s * LW_SEG + r * (AP * 2) + j * 16);
        cp_async16(sb + SM_WH + dst, whh_h + src);
        cp_async16(sb + SM_WL + dst, whh_l + src);
    }
    cp_async_commit();
    CP_WAITN(0);
    __syncthreads();

    const int seg = wid;
    const uint32_t a_off = (uint32_t)(((lane & 15) * AP + (lane >> 4) * 8) * 2);
    uint32_t Afh[4][2][4], Afl[4][2][4];
    #pragma unroll
    for (int g = 0; g < 4; g++) {
        #pragma unroll
        for (int ks = 0; ks < 2; ks++) {
            uint32_t aa = sb + (uint32_t)(seg * LW_SEG + g * 16 * AP * 2) + a_off
                        + (uint32_t)(ks * 32);
            LDSM_X4(Afh[g][ks][0], Afh[g][ks][1], Afh[g][ks][2], Afh[g][ks][3], aa);
            LDSM_X4(Afl[g][ks][0], Afl[g][ks][1], Afl[g][ks][2], Afl[g][ks][3],
                    aa + (uint32_t)(SM_WL - SM_WH));
        }
    }

    const uint32_t b_off = (uint32_t)(((lane & 7) * AP + ((lane >> 3) & 1) * 8) * 2);

    const int acolL = tid >> 3;
    const int ab    = tid & 7;
    const int gcol  = col_base + acolL;
    const int abatch = group * 8 + ab;
    const int hseg  = gcol >> 5;
    const int hc32  = gcol & 31;
    const size_t xgb = (size_t)(abatch * TT) * (4 * HH) + gcol;
    unsigned* my_flag = &g_flags[blockIdx.x * 64];
    float c_reg = 0.f;

    const __nv_bfloat16* hbh_rd[2] = { g_hbh[0] + group * 4096, g_hbh[1] + group * 4096 };
    const __nv_bfloat16* hbl_rd[2] = { g_hbl[0] + group * 4096, g_hbl[1] + group * 4096 };
    __nv_bfloat16* hbh_wr[2] = { g_hbh[0] + group * 4096, g_hbh[1] + group * 4096 };
    __nv_bfloat16* hbl_wr[2] = { g_hbl[0] + group * 4096, g_hbl[1] + group * 4096 };

    for (int t = 0; t < TT; t++) {
        const int rb = t & 1;
        const int wb = rb ^ 1;

        if (t > 0) {
            if (tid < 32) {
                const unsigned* fp = &g_flags[(group * 32 + tid) * 64];
                unsigned v;
                do {
                    asm volatile("ld.acquire.gpu.global.u32 %0, [%1];"
                                 : "=r"(v) : "l"(fp) : "memory");
                } while (v < (unsigned)t);
            }
            __syncthreads();
        }

        #pragma unroll
        for (int i = 0; i < 2; i++) {
            int it = tid + i * 512;
            int m  = it >> 9;
            int idx = it & 511;
            int s = idx >> 5, b = (idx >> 2) & 7, j = idx & 3;
            const __nv_bfloat16* src = (m ? hbl_rd[rb] : hbh_rd[rb])
                                     + s * 256 + b * 32 + j * 8;
            uint32_t dst = sb + (uint32_t)(m ? SM_HL : SM_HH)
                         + (uint32_t)(s * LH_SEG + b * (AP * 2) + j * 16);
            cp_async16(dst, src);
        }
        cp_async_commit();

        float xv0 = 0.f, xv1 = 0.f, xv2 = 0.f, xv3 = 0.f;
        if (tid < 128) {
            const float* xp = xg + xgb + (size_t)t * (4 * HH);
            xv0 = __ldg(xp);
            xv1 = __ldg(xp + HH);
            xv2 = __ldg(xp + 2 * HH);
            xv3 = __ldg(xp + 3 * HH);
        }

        CP_WAITN(0);
        __syncthreads();

        float acc[4][4];
        #pragma unroll
        for (int g = 0; g < 4; g++)
            #pragma unroll
            for (int r = 0; r < 4; r++) acc[g][r] = 0.f;

        #pragma unroll
        for (int ks = 0; ks < 2; ks++) {
            uint32_t ba = sb + SM_HH + (uint32_t)(seg * LH_SEG) + b_off + (uint32_t)(ks * 32);
            uint32_t bh[2], bl[2];
            LDSM_X2(bh[0], bh[1], ba);
            LDSM_X2(bl[0], bl[1], ba + (uint32_t)(SM_HL - SM_HH));
            #pragma unroll
            for (int g = 0; g < 4; g++) {
                MMA16816(acc[g], Afh[g][ks], bh);
                MMA16816(acc[g], Afh[g][ks], bl);
                MMA16816(acc[g], Afl[g][ks], bh);
            }
        }

        {
            const int tm = lane >> 2;
            const int tc = (lane & 3) * 2;
            float* rp = red + wid * 513;
            #pragma unroll
            for (int g = 0; g < 4; g++) {
                rp[g * 128 + tm * 8 + tc]           = acc[g][0];
                rp[g * 128 + tm * 8 + tc + 1]       = acc[g][1];
                rp[g * 128 + (tm + 8) * 8 + tc]     = acc[g][2];
                rp[g * 128 + (tm + 8) * 8 + tc + 1] = acc[g][3];
            }
        }
        __syncthreads();

        if (tid < 128) {
            const int p = acolL * 8 + ab;
            float gv[4] = { xv0, xv1, xv2, xv3 };
            #pragma unroll
            for (int w = 0; w < 16; w++) {
                const float* rp = red + w * 513 + p;
                gv[0] += rp[0];
                gv[1] += rp[128];
                gv[2] += rp[256];
                gv[3] += rp[384];
            }
            float ig = 1.f / (1.f + __expf(-gv[0]));
            float fg = 1.f / (1.f + __expf(-gv[1]));
            float gg = tanhf(gv[2]);
            float og = 1.f / (1.f + __expf(-gv[3]));
            c_reg = fg * c_reg + ig * gg;
            float hn = og * tanhf(c_reg);
            lstm_out[(size_t)(abatch * TT + t) * HH + gcol] = hn;
            __nv_bfloat16 hh_, hl_;
            split1(hn, hh_, hl_);
            int off = hseg * 256 + ab * 32 + hc32;
            st_bf16_cg(hbh_wr[wb] + off, hh_);
            st_bf16_cg(hbl_wr[wb] + off, hl_);
        }
        __syncthreads();

        if (tid == 0) {
            asm volatile("fence.acq_rel.gpu;" ::: "memory");
            asm volatile("st.release.gpu.global.u32 [%0], %1;"
                         :: "l"(my_flag), "r"((unsigned)(t + 1)) : "memory");
        }
    }
}

// ---------------- fused attention (packed kv input, bf16 hi/lo ctx output) ----------------
#define KTP 257
#define QSP 68
#define PSP 260
__global__ __launch_bounds__(256) void attn_kernel(
    const float* __restrict__ q, const float* __restrict__ kv,
    __nv_bfloat16* __restrict__ ctxh, __nv_bfloat16* __restrict__ ctxl)
{
    extern __shared__ float smemf[];
    float* Kt   = smemf;
    float* Vt   = Kt + 64 * KTP;
    float* qs   = Vt + 64 * KTP;
    float* ps   = qs + 32 * QSP;
    float* sums = ps + 32 * PSP;

    const int t0 = blockIdx.x * 32;
    const int h  = blockIdx.y;
    const int b  = blockIdx.z;
    const int tid = threadIdx.x;

    for (int idx = tid; idx < 256 * 16; idx += 256) {
        int s = idx >> 4; int d4 = (idx & 15) << 2;
        size_t off = (size_t)(b * SS + s) * 1024 + h * HDD + d4;
        float4 kvv = *(const float4*)(kv + off);
        Kt[(d4 + 0) * KTP + s] = kvv.x; Kt[(d4 + 1) * KTP + s] = kvv.y;
        Kt[(d4 + 2) * KTP + s] = kvv.z; Kt[(d4 + 3) * KTP + s] = kvv.w;
        float4 vvv = *(const float4*)(kv + off + 512);
        Vt[(d4 + 0) * KTP + s] = vvv.x; Vt[(d4 + 1) * KTP + s] = vvv.y;
        Vt[(d4 + 2) * KTP + s] = vvv.z; Vt[(d4 + 3) * KTP + s] = vvv.w;
    }
    for (int idx = tid; idx < 32 * 16; idx += 256) {
        int r = idx >> 4; int d4 = (idx & 15) << 2;
        int trow = t0 + r;
        float4 qv = make_float4(0.f, 0.f, 0.f, 0.f);
        if (trow < TT)
            qv = *(const float4*)(q + (size_t)(b * TT + trow) * HH + h * HDD + d4);
        float* d = qs + r * QSP + d4;
        d[0] = qv.x; d[1] = qv.y; d[2] = qv.z; d[3] = qv.w;
    }
    __syncthreads();

    const int r  = tid >> 3;
    const int lc = tid & 7;

    float qreg[64];
    #pragma unroll
    for (int d = 0; d < 64; d++) qreg[d] = qs[r * QSP + d];

    float sc[32];
    for (int si = 0; si < 32; si++) {
        int s = si * 8 + lc;
        float acc = 0.f;
        #pragma unroll
        for (int d = 0; d < 64; d++) acc += qreg[d] * Kt[d * KTP + s];
        sc[si] = acc * 0.125f;
    }
    float m = -1e30f;
    #pragma unroll
    for (int si = 0; si < 32; si++) m = fmaxf(m, sc[si]);
    m = fmaxf(m, __shfl_xor_sync(0xffffffff, m, 1));
    m = fmaxf(m, __shfl_xor_sync(0xffffffff, m, 2));
    m = fmaxf(m, __shfl_xor_sync(0xffffffff, m, 4));
    float ssum = 0.f;
    #pragma unroll
    for (int si = 0; si < 32; si++) {
        float e = __expf(sc[si] - m);
        ssum += e;
        ps[r * PSP + si * 8 + lc] = e;
    }
    ssum += __shfl_xor_sync(0xffffffff, ssum, 1);
    ssum += __shfl_xor_sync(0xffffffff, ssum, 2);
    ssum += __shfl_xor_sync(0xffffffff, ssum, 4);
    if (lc == 0) sums[r] = ssum;
    __syncthreads();

    float accv[8];
    #pragma unroll
    for (int j = 0; j < 8; j++) accv[j] = 0.f;
    const float* prow = ps + r * PSP;
    #pragma unroll 4
    for (int s = 0; s < 256; s++) {
        float pv = prow[s];
        #pragma unroll
        for (int j = 0; j < 8; j++)
            accv[j] += pv * Vt[(lc + 8 * j) * KTP + s];
    }
    float inv = 1.0f / sums[r];
    int trow = t0 + r;
    if (trow < TT) {
        size_t base = (size_t)(b * TT + trow) * HH + h * HDD;
        #pragma unroll
        for (int j = 0; j < 8; j++) {
            float val = accv[j] * inv;
            __nv_bfloat16 hv, lv;
            split1(val, hv, lv);
            ctxh[base + lc + 8 * j] = hv;
            ctxl[base + lc + 8 * j] = lv;
        }
    }
}

// ---------------- launch ----------------
extern "C" void kernel_launch(void* const* d_in, const int* in_sizes, int n_in,
                              void* d_out, int out_size) {
    const int*   targets  = (const int*)  d_in[0];
    const float* enc      = (const float*)d_in[1];
    const float* embedding= (const float*)d_in[2];
    const float* w_ih     = (const float*)d_in[3];
    const float* w_hh     = (const float*)d_in[4];
    const float* b_ih     = (const float*)d_in[5];
    const float* b_hh     = (const float*)d_in[6];
    const float* in_proj_w= (const float*)d_in[7];
    const float* in_proj_b= (const float*)d_in[8];
    const float* out_proj_w=(const float*)d_in[9];
    const float* out_proj_b=(const float*)d_in[10];
    const float* fc_w     = (const float*)d_in[11];
    const float* fc_b     = (const float*)d_in[12];
    float* out = (float*)d_out;

    float *p_xg, *p_lstm, *p_q, *p_kv;
    cudaGetSymbolAddress((void**)&p_xg,   g_xg);
    cudaGetSymbolAddress((void**)&p_lstm, g_lstm);
    cudaGetSymbolAddress((void**)&p_q,    g_q);
    cudaGetSymbolAddress((void**)&p_kv,   g_kv);
    __nv_bfloat16 *p_embh, *p_embl, *p_lstmh, *p_lstml, *p_ctxh, *p_ctxl,
                  *p_combh, *p_combl, *p_ench, *p_encl, *p_wihh, *p_wihl,
                  *p_whhh, *p_whhl, *p_inph, *p_inpl, *p_outph, *p_outpl,
                  *p_fcwh, *p_fcwl;
    cudaGetSymbolAddress((void**)&p_embh,  g_embh);
    cudaGetSymbolAddress((void**)&p_embl,  g_embl);
    cudaGetSymbolAddress((void**)&p_lstmh, g_lstmh);
    cudaGetSymbolAddress((void**)&p_lstml, g_lstml);
    cudaGetSymbolAddress((void**)&p_ctxh,  g_ctxh);
    cudaGetSymbolAddress((void**)&p_ctxl,  g_ctxl);
    cudaGetSymbolAddress((void**)&p_combh, g_combh);
    cudaGetSymbolAddress((void**)&p_combl, g_combl);
    cudaGetSymbolAddress((void**)&p_ench,  g_ench);
    cudaGetSymbolAddress((void**)&p_encl,  g_encl);
    cudaGetSymbolAddress((void**)&p_wihh,  g_wihh);
    cudaGetSymbolAddress((void**)&p_wihl,  g_wihl);
    cudaGetSymbolAddress((void**)&p_whhh,  g_whhh);
    cudaGetSymbolAddress((void**)&p_whhl,  g_whhl);
    cudaGetSymbolAddress((void**)&p_inph,  g_inph);
    cudaGetSymbolAddress((void**)&p_inpl,  g_inpl);
    cudaGetSymbolAddress((void**)&p_outph, g_outph);
    cudaGetSymbolAddress((void**)&p_outpl, g_outpl);
    cudaGetSymbolAddress((void**)&p_fcwh,  g_fcwh);
    cudaGetSymbolAddress((void**)&p_fcwl,  g_fcwl);

    const int attn_smem = (64 * KTP * 2 + 32 * QSP + 32 * PSP + 32) * (int)sizeof(float);
    const int mma_smem  = 8 * SEG;
    cudaFuncSetAttribute(attn_kernel,     cudaFuncAttributeMaxDynamicSharedMemorySize, attn_smem);
    cudaFuncSetAttribute(mma_gemm,        cudaFuncAttributeMaxDynamicSharedMemorySize, mma_smem);
    cudaFuncSetAttribute(lstm_mma_kernel, cudaFuncAttributeMaxDynamicSharedMemorySize, LSTM_SMEM);

    #define SPLIT(src, hi, lo, n) split_kernel<<<((n)/4 + 255) / 256, 256>>>(src, hi, lo, n)

    // 1. zero h0 + flags
    zero_kernel<<<(2 * 4 * 4096 + 255) / 256, 256>>>();

    // 2. weight/input splits
    SPLIT(w_ih,       p_wihh,  p_wihl,  4 * HH * HH);
    SPLIT(w_hh,       p_whhh,  p_whhl,  4 * HH * HH);
    SPLIT(in_proj_w,  p_inph,  p_inpl,  3 * HH * HH);
    SPLIT(out_proj_w, p_outph, p_outpl, HH * HH);
    SPLIT(fc_w,       p_fcwh,  p_fcwl,  VV * HH);
    SPLIT(enc,        p_ench,  p_encl,  BS * HH);

    // 3. gather embeddings (fused split)
    gather_split_kernel<<<BT, 128>>>(targets, embedding, p_embh, p_embl);

    // 4. xg = emb @ w_ih^T + b_ih + b_hh
    {
        dim3 grid(4 * HH / 128, MPAD / 128);
        mma_gemm<<<grid, 256, mma_smem>>>(p_embh, p_embl, p_wihh, p_wihl,
                                          b_ih, b_hh, nullptr, p_xg, nullptr, nullptr,
                                          BT, 4 * HH, HH);
    }

    // 5. LSTM recurrence (lean step loop; split done once afterwards)
    lstm_mma_kernel<<<NBLK, 512, LSTM_SMEM>>>(p_xg, p_whhh, p_whhl, p_lstm);
    SPLIT(p_lstm, p_lstmh, p_lstml, BT * HH);

    // 6. q projection + merged K|V projection
    {
        dim3 gq(HH / 128, MPAD / 128);
        mma_gemm<<<gq, 256, mma_smem>>>(p_lstmh, p_lstml, p_inph, p_inpl,
                                        in_proj_b, nullptr, nullptr, p_q, nullptr, nullptr,
                                        BT, HH, HH);
        dim3 gkv(1024 / 128, BS / 128);
        mma_gemm<<<gkv, 256, mma_smem>>>(p_ench, p_encl, p_inph + (size_t)HH * HH,
                                         p_inpl + (size_t)HH * HH,
                                         in_proj_b + HH, nullptr, nullptr, p_kv,
                                         nullptr, nullptr, BS, 1024, HH);
    }

    // 7. fused attention -> ctx hi/lo
    {
        dim3 grid(4, NHH, BB);
        attn_kernel<<<grid, 256, attn_smem>>>(p_q, p_kv, p_ctxh, p_ctxl);
    }

    // 8. combined = ctx @ out_proj^T + out_proj_b + lstm_out  (direct bf16 hi/lo output)
    {
        dim3 grid(HH / 128, MPAD / 128);
        mma_gemm<<<grid, 256, mma_smem>>>(p_ctxh, p_ctxl, p_outph, p_outpl,
                                          out_proj_b, nullptr, p_lstm, nullptr,
                                          p_combh, p_combl, BT, HH, HH);
    }

    // 9. out = combined @ fc_w^T + fc_b
    {
        dim3 grid(VPAD / 128, MPAD / 128);
        mma_gemm<<<grid, 256, mma_smem>>>(p_combh, p_combl, p_fcwh, p_fcwl,
                                          fc_b, nullptr, nullptr, out, nullptr, nullptr,
                                          BT, VV, HH);
    }
    #undef SPLIT
}

// round 15
// speedup vs baseline: 1.1032x; 1.0684x over previous
#include <cuda_runtime.h>
#include <cuda_bf16.h>
#include <math.h>
#include <stdint.h>
#include <string.h>

// Problem constants
#define BB   32
#define TT   127
#define SS   256
#define HH   512
#define VV   8000
#define NHH  8
#define HDD  64
#define BT   (BB*TT)      // 4064
#define BS   (BB*SS)      // 8192
#define NBLK 128          // persistent LSTM grid (4 groups x 32 blocks)
#define MPAD 4096
#define VPAD 8064

// ---------------- scratch (device globals; no allocations allowed) ----------------
__device__ float g_xg  [BT * 4 * HH];
__device__ float g_lstm[BT * HH];
__device__ float g_q   [BT * HH];
__device__ float g_kv  [BS * 1024];           // packed K(0..511) | V(512..1023)
__device__ float g_ctx [BT * HH];
__device__ float g_comb[BT * HH];
__device__ unsigned g_flags[NBLK * 2 * 32];

// bf16 hi/lo split buffers (pads stay zero)
__device__ __nv_bfloat16 g_embh [MPAD * HH], g_embl [MPAD * HH];
__device__ __nv_bfloat16 g_lstmh[MPAD * HH], g_lstml[MPAD * HH];
__device__ __nv_bfloat16 g_ctxh [MPAD * HH], g_ctxl [MPAD * HH];
__device__ __nv_bfloat16 g_combh[MPAD * HH], g_combl[MPAD * HH];
__device__ __nv_bfloat16 g_ench [BS * HH],   g_encl [BS * HH];
__device__ __nv_bfloat16 g_wihh [4*HH*HH],   g_wihl [4*HH*HH];
__device__ __nv_bfloat16 g_whhh [4*HH*HH],   g_whhl [4*HH*HH];
__device__ __nv_bfloat16 g_inph [3*HH*HH],   g_inpl [3*HH*HH];
__device__ __nv_bfloat16 g_outph[HH*HH],     g_outpl[HH*HH];
__device__ __nv_bfloat16 g_fcwh [VPAD * HH], g_fcwl [VPAD * HH];
// LSTM h ping-pong, bf16 hi/lo, B-operand packed layout
__device__ __nv_bfloat16 g_hbh[2][4 * 4096];
__device__ __nv_bfloat16 g_hbl[2][4 * 4096];

// ---------------- cp.async helpers ----------------
__device__ __forceinline__ void cp_async16(uint32_t dst_smem, const void* src_gmem) {
    asm volatile("cp.async.cg.shared.global [%0], [%1], 16;\n" :: "r"(dst_smem), "l"(src_gmem));
}
__device__ __forceinline__ void cp_async_commit() { asm volatile("cp.async.commit_group;\n"); }
#define CP_WAITN(n) asm volatile("cp.async.wait_group %0;\n" :: "n"(n))

__device__ __forceinline__ uint32_t s2u(const void* p) {
    uint32_t a;
    asm("{ .reg .u64 t; cvta.to.shared.u64 t, %1; cvt.u32.u64 %0, t; }" : "=r"(a) : "l"(p));
    return a;
}
__device__ __forceinline__ void st_bf16_cg(__nv_bfloat16* p, __nv_bfloat16 v) {
    unsigned short u; memcpy(&u, &v, 2);
    asm volatile("st.global.cg.u16 [%0], %1;" :: "l"(p), "h"(u) : "memory");
}
__device__ __forceinline__ void split1(float v, __nv_bfloat16& h, __nv_bfloat16& l) {
    h = __float2bfloat16_rn(v);
    l = __float2bfloat16_rn(v - __bfloat162float(h));
}

// ---------------- mma helpers ----------------
#define LDSM_X4(r0, r1, r2, r3, addr)                                              \
    asm volatile("ldmatrix.sync.aligned.m8n8.x4.shared.b16 {%0,%1,%2,%3}, [%4];"   \
        : "=r"(r0), "=r"(r1), "=r"(r2), "=r"(r3) : "r"(addr))
#define LDSM_X2(r0, r1, addr)                                                      \
    asm volatile("ldmatrix.sync.aligned.m8n8.x2.shared.b16 {%0,%1}, [%2];"         \
        : "=r"(r0), "=r"(r1) : "r"(addr))
#define MMA16816(d, a, b)                                                          \
    asm volatile("mma.sync.aligned.m16n8k16.row.col.f32.bf16.bf16.f32 "            \
        "{%0,%1,%2,%3},{%4,%5,%6,%7},{%8,%9},{%0,%1,%2,%3};"                       \
        : "+f"((d)[0]), "+f"((d)[1]), "+f"((d)[2]), "+f"((d)[3])                   \
        : "r"((a)[0]), "r"((a)[1]), "r"((a)[2]), "r"((a)[3]),                      \
          "r"((b)[0]), "r"((b)[1]))

// ---------------- init: zero h0 (bf16 buffers) and flags ----------------
__global__ void zero_kernel() {
    int i = blockIdx.x * blockDim.x + threadIdx.x;
    if (i < 2 * 4 * 4096) {
        ((__nv_bfloat16*)g_hbh)[i] = __float2bfloat16(0.f);
        ((__nv_bfloat16*)g_hbl)[i] = __float2bfloat16(0.f);
    }
    if (i < NBLK * 2 * 32) g_flags[i] = 0u;
}

// ---------------- embedding gather fused with hi/lo split ----------------
__global__ void gather_split_kernel(const int* __restrict__ targets,
                                    const float* __restrict__ table,
                                    __nv_bfloat16* __restrict__ hi,
                                    __nv_bfloat16* __restrict__ lo) {
    int bt = blockIdx.x;
    int b = bt / TT, t = bt - b * TT;
    int tok = targets[b * 128 + t];
    int j = threadIdx.x;                      // 0..127, 4 floats each
    float4 v = ((const float4*)(table + (size_t)tok * HH))[j];
    __nv_bfloat16 hx, hy, hz, hw, lx, ly, lz, lw;
    split1(v.x, hx, lx); split1(v.y, hy, ly);
    split1(v.z, hz, lz); split1(v.w, hw, lw);
    size_t o = (size_t)bt * HH + j * 4;
    *(__nv_bfloat162*)(hi + o)     = __halves2bfloat162(hx, hy);
    *(__nv_bfloat162*)(hi + o + 2) = __halves2bfloat162(hz, hw);
    *(__nv_bfloat162*)(lo + o)     = __halves2bfloat162(lx, ly);
    *(__nv_bfloat162*)(lo + o + 2) = __halves2bfloat162(lz, lw);
}

// ---------------- fp32 -> bf16 hi/lo split ----------------
__global__ void split_kernel(const float* __restrict__ x,
                             __nv_bfloat16* __restrict__ hi,
                             __nv_bfloat16* __restrict__ lo, int n) {
    int i4 = (blockIdx.x * blockDim.x + threadIdx.x) * 4;
    if (i4 < n) {
        float4 v = *(const float4*)(x + i4);
        __nv_bfloat16 hx, hy, hz, hw, lx, ly, lz, lw;
        split1(v.x, hx, lx); split1(v.y, hy, ly);
        split1(v.z, hz, lz); split1(v.w, hw, lw);
        *(__nv_bfloat162*)(hi + i4)     = __halves2bfloat162(hx, hy);
        *(__nv_bfloat162*)(hi + i4 + 2) = __halves2bfloat162(hz, hw);
        *(__nv_bfloat162*)(lo + i4)     = __halves2bfloat162(lx, ly);
        *(__nv_bfloat162*)(lo + i4 + 2) = __halves2bfloat162(lz, lw);
    }
}

// ---------------- tensor-core GEMM via mma.sync (exact R11 version) ----------------
#define AP   40
#define SEG  (128 * AP * 2)
__global__ __launch_bounds__(256) void mma_gemm(
    const __nv_bfloat16* __restrict__ Ah, const __nv_bfloat16* __restrict__ Al,
    const __nv_bfloat16* __restrict__ Bh, const __nv_bfloat16* __restrict__ Bl,
    const float* __restrict__ bias1, const float* __restrict__ bias2,
    const float* __restrict__ res, float* __restrict__ C,
    int M, int N, int K)
{
    extern __shared__ char smem[];
    const uint32_t sb = s2u(smem);
    const int tid  = threadIdx.x;
    const int wid  = tid >> 5;
    const int lane = tid & 31;
    const int wm = wid >> 2;
    const int wn = wid & 3;
    const int m0 = blockIdx.y * 128;
    const int n0 = blockIdx.x * 128;

    float acc[4][4][4];
    #pragma unroll
    for (int i = 0; i < 4; i++)
        #pragma unroll
        for (int j = 0; j < 4; j++)
            #pragma unroll
            for (int r = 0; r < 4; r++) acc[i][j][r] = 0.f;

    const __nv_bfloat16* srcAh = Ah + (size_t)m0 * K;
    const __nv_bfloat16* srcAl = Al + (size_t)m0 * K;
    const __nv_bfloat16* srcBh = Bh + (size_t)n0 * K;
    const __nv_bfloat16* srcBl = Bl + (size_t)n0 * K;

    auto issue = [&](int k0, int buf) {
        #pragma unroll
        for (int t = 0; t < 8; t++) {
            int idx = tid + t * 256;
            int mat = idx >> 9;
            int r   = (idx >> 2) & 127;
            int j   = idx & 3;
            uint32_t dst = sb + (uint32_t)(mat * 2 + buf) * SEG
                         + (uint32_t)(r * AP + j * 8) * 2;
            const __nv_bfloat16* s =
                (mat == 0 ? srcAh : mat == 1 ? srcAl : mat == 2 ? srcBh : srcBl)
                + (size_t)r * K + k0 + j * 8;
            cp_async16(dst, s);
        }
        cp_async_commit();
    };

    const uint32_t a_off = (uint32_t)(((wm * 64 + (lane & 15)) * AP + (lane >> 4) * 8) * 2);
    const uint32_t b_off = (uint32_t)(((wn * 32 + (lane & 7)) * AP + ((lane >> 3) & 1) * 8) * 2);

    const int NC = K / 32;
    issue(0, 0);
    #pragma unroll 1
    for (int c = 0; c < NC; c++) {
        const int buf = c & 1;
        if (c + 1 < NC) { issue((c + 1) * 32, buf ^ 1); CP_WAITN(1); }
        else           { CP_WAITN(0); }
        __syncthreads();

        #pragma unroll
        for (int ks = 0; ks < 2; ks++) {
            const uint32_t kb = (uint32_t)(ks * 32);
            uint32_t bh[4][2], bl[4][2];
            #pragma unroll
            for (int nt = 0; nt < 4; nt++) {
                uint32_t ba = sb + (uint32_t)(4 + buf) * SEG + b_off
                            + (uint32_t)(nt * 8 * AP * 2) + kb;
                LDSM_X2(bh[nt][0], bh[nt][1], ba);
                LDSM_X2(bl[nt][0], bl[nt][1], ba + 2u * SEG);
            }
            #pragma unroll
            for (int mt = 0; mt < 4; mt++) {
                uint32_t ah[4], al[4];
                uint32_t aa = sb + (uint32_t)buf * SEG + a_off
                            + (uint32_t)(mt * 16 * AP * 2) + kb;
                LDSM_X4(ah[0], ah[1], ah[2], ah[3], aa);
                LDSM_X4(al[0], al[1], al[2], al[3], aa + 2u * SEG);
                #pragma unroll
                for (int nt = 0; nt < 4; nt++) {
                    MMA16816(acc[mt][nt], ah, bh[nt]);
                    MMA16816(acc[mt][nt], ah, bl[nt]);
                    MMA16816(acc[mt][nt], al, bh[nt]);
                }
            }
        }
        __syncthreads();
    }

    const int tm = lane >> 2;
    const int tc = (lane & 3) * 2;
    #pragma unroll
    for (int mt = 0; mt < 4; mt++) {
        #pragma unroll
        for (int nt = 0; nt < 4; nt++) {
            int col = n0 + wn * 32 + nt * 8 + tc;
            if (col >= N) continue;
            float2 v0 = make_float2(acc[mt][nt][0], acc[mt][nt][1]);
            float2 v1 = make_float2(acc[mt][nt][2], acc[mt][nt][3]);
            if (bias1) {
                float2 b = *(const float2*)(bias1 + col);
                v0.x += b.x; v0.y += b.y; v1.x += b.x; v1.y += b.y;
            }
            if (bias2) {
                float2 b = *(const float2*)(bias2 + col);
                v0.x += b.x; v0.y += b.y; v1.x += b.x; v1.y += b.y;
            }
            int row0 = m0 + wm * 64 + mt * 16 + tm;
            if (row0 < M) {
                float2 o = v0;
                if (res) {
                    float2 rr = *(const float2*)(res + (size_t)row0 * N + col);
                    o.x += rr.x; o.y += rr.y;
                }
                *(float2*)(C + (size_t)row0 * N + col) = o;
            }
            int row1 = row0 + 8;
            if (row1 < M) {
                float2 o = v1;
                if (res) {
                    float2 rr = *(const float2*)(res + (size_t)row1 * N + col);
                    o.x += rr.x; o.y += rr.y;
                }
                *(float2*)(C + (size_t)row1 * N + col) = o;
            }
        }
    }
}

// ---------------- tensor-core persistent LSTM (exact R11 version) ----------------
#define LW_SEG  (64 * AP * 2)
#define LH_SEG  (8 * AP * 2)
#define SM_WH   0
#define SM_WL   81920
#define SM_HH   163840
#define SM_HL   174080
#define SM_RED  184320
#define LSTM_SMEM (SM_RED + 16 * 513 * 4)

__global__ __launch_bounds__(512) void lstm_mma_kernel(
    const float* __restrict__ xg,
    const __nv_bfloat16* __restrict__ whh_h, const __nv_bfloat16* __restrict__ whh_l,
    float* __restrict__ lstm_out)
{
    extern __shared__ char smem[];
    const uint32_t sb = s2u(smem);
    float* red = (float*)(smem + SM_RED);

    const int tid   = threadIdx.x;
    const int wid   = tid >> 5;
    const int lane  = tid & 31;
    const int group = blockIdx.x >> 5;
    const int gslot = blockIdx.x & 31;
    const int col_base = gslot * 16;

    for (int it = tid; it < 16 * 64 * 4; it += 512) {
        int s = it >> 8;
        int r = (it >> 2) & 63;
        int j = it & 3;
        int gate = r >> 4, colL = r & 15;
        size_t src = (size_t)(gate * HH + col_base + colL) * HH + s * 32 + j * 8;
        uint32_t dst = (uint32_t)(s * LW_SEG + r * (AP * 2) + j * 16);
        cp_async16(sb + SM_WH + dst, whh_h + src);
        cp_async16(sb + SM_WL + dst, whh_l + src);
    }
    cp_async_commit();
    CP_WAITN(0);
    __syncthreads();

    const int seg = wid;
    const uint32_t a_off = (uint32_t)(((lane & 15) * AP + (lane >> 4) * 8) * 2);
    uint32_t Afh[4][2][4], Afl[4][2][4];
    #pragma unroll
    for (int g = 0; g < 4; g++) {
        #pragma unroll
        for (int ks = 0; ks < 2; ks++) {
            uint32_t aa = sb + (uint32_t)(seg * LW_SEG + g * 16 * AP * 2) + a_off
                        + (uint32_t)(ks * 32);
            LDSM_X4(Afh[g][ks][0], Afh[g][ks][1], Afh[g][ks][2], Afh[g][ks][3], aa);
            LDSM_X4(Afl[g][ks][0], Afl[g][ks][1], Afl[g][ks][2], Afl[g][ks][3],
                    aa + (uint32_t)(SM_WL - SM_WH));
        }
    }

    const uint32_t b_off = (uint32_t)(((lane & 7) * AP + ((lane >> 3) & 1) * 8) * 2);

    const int acolL = tid >> 3;
    const int ab    = tid & 7;
    const int gcol  = col_base + acolL;
    const int abatch = group * 8 + ab;
    const int hseg  = gcol >> 5;
    const int hc32  = gcol & 31;
    const size_t xgb = (size_t)(abatch * TT) * (4 * HH) + gcol;
    unsigned* my_flag = &g_flags[blockIdx.x * 64];
    float c_reg = 0.f;

    const __nv_bfloat16* hbh_rd[2] = { g_hbh[0] + group * 4096, g_hbh[1] + group * 4096 };
    const __nv_bfloat16* hbl_rd[2] = { g_hbl[0] + group * 4096, g_hbl[1] + group * 4096 };
    __nv_bfloat16* hbh_wr[2] = { g_hbh[0] + group * 4096, g_hbh[1] + group * 4096 };
    __nv_bfloat16* hbl_wr[2] = { g_hbl[0] + group * 4096, g_hbl[1] + group * 4096 };

    for (int t = 0; t < TT; t++) {
        const int rb = t & 1;
        const int wb = rb ^ 1;

        if (t > 0) {
            if (tid < 32) {
                const unsigned* fp = &g_flags[(group * 32 + tid) * 64];
                unsigned v;
                do {
                    asm volatile("ld.acquire.gpu.global.u32 %0, [%1];"
                                 : "=r"(v) : "l"(fp) : "memory");
                } while (v < (unsigned)t);
            }
            __syncthreads();
        }

        #pragma unroll
        for (int i = 0; i < 2; i++) {
            int it = tid + i * 512;
            int m  = it >> 9;
            int idx = it & 511;
            int s = idx >> 5, b = (idx >> 2) & 7, j = idx & 3;
            const __nv_bfloat16* src = (m ? hbl_rd[rb] : hbh_rd[rb])
                                     + s * 256 + b * 32 + j * 8;
            uint32_t dst = sb + (uint32_t)(m ? SM_HL : SM_HH)
                         + (uint32_t)(s * LH_SEG + b * (AP * 2) + j * 16);
            cp_async16(dst, src);
        }
        cp_async_commit();

        float xv0 = 0.f, xv1 = 0.f, xv2 = 0.f, xv3 = 0.f;
        if (tid < 128) {
            const float* xp = xg + xgb + (size_t)t * (4 * HH);
            xv0 = __ldg(xp);
            xv1 = __ldg(xp + HH);
            xv2 = __ldg(xp + 2 * HH);
            xv3 = __ldg(xp + 3 * HH);
        }

        CP_WAITN(0);
        __syncthreads();

        float acc[4][4];
        #pragma unroll
        for (int g = 0; g < 4; g++)
            #pragma unroll
            for (int r = 0; r < 4; r++) acc[g][r] = 0.f;

        #pragma unroll
        for (int ks = 0; ks < 2; ks++) {
            uint32_t ba = sb + SM_HH + (uint32_t)(seg * LH_SEG) + b_off + (uint32_t)(ks * 32);
            uint32_t bh[2], bl[2];
            LDSM_X2(bh[0], bh[1], ba);
            LDSM_X2(bl[0], bl[1], ba + (uint32_t)(SM_HL - SM_HH));
            #pragma unroll
            for (int g = 0; g < 4; g++) {
                MMA16816(acc[g], Afh[g][ks], bh);
                MMA16816(acc[g], Afh[g][ks], bl);
                MMA16816(acc[g], Afl[g][ks], bh);
            }
        }

        {
            const int tm = lane >> 2;
            const int tc = (lane & 3) * 2;
            float* rp = red + wid * 513;
            #pragma unroll
            for (int g = 0; g < 4; g++) {
                rp[g * 128 + tm * 8 + tc]           = acc[g][0];
                rp[g * 128 + tm * 8 + tc + 1]       = acc[g][1];
                rp[g * 128 + (tm + 8) * 8 + tc]     = acc[g][2];
                rp[g * 128 + (tm + 8) * 8 + tc + 1] = acc[g][3];
            }
        }
        __syncthreads();

        if (tid < 128) {
            const int p = acolL * 8 + ab;
            float gv[4] = { xv0, xv1, xv2, xv3 };
            #pragma unroll
            for (int w = 0; w < 16; w++) {
                const float* rp = red + w * 513 + p;
                gv[0] += rp[0];
                gv[1] += rp[128];
                gv[2] += rp[256];
                gv[3] += rp[384];
            }
            float ig = 1.f / (1.f + __expf(-gv[0]));
            float fg = 1.f / (1.f + __expf(-gv[1]));
            float gg = tanhf(gv[2]);
            float og = 1.f / (1.f + __expf(-gv[3]));
            c_reg = fg * c_reg + ig * gg;
            float hn = og * tanhf(c_reg);
            lstm_out[(size_t)(abatch * TT + t) * HH + gcol] = hn;
            __nv_bfloat16 hh_, hl_;
            split1(hn, hh_, hl_);
            int off = hseg * 256 + ab * 32 + hc32;
            st_bf16_cg(hbh_wr[wb] + off, hh_);
            st_bf16_cg(hbl_wr[wb] + off, hl_);
        }
        __syncthreads();

        if (tid == 0) {
            asm volatile("fence.acq_rel.gpu;" ::: "memory");
            asm volatile("st.release.gpu.global.u32 [%0], %1;"
                         :: "l"(my_flag), "r"((unsigned)(t + 1)) : "memory");
        }
    }
}

// ---------------- fused attention (packed kv input, fp32 ctx output — R11 math) ----------------
#define KTP 257
#define QSP 68
#define PSP 260
__global__ __launch_bounds__(256) void attn_kernel(
    const float* __restrict__ q, const float* __restrict__ kv,
    float* __restrict__ ctx)
{
    extern __shared__ float smemf[];
    float* Kt   = smemf;
    float* Vt   = Kt + 64 * KTP;
    float* qs   = Vt + 64 * KTP;
    float* ps   = qs + 32 * QSP;
    float* sums = ps + 32 * PSP;

    const int t0 = blockIdx.x * 32;
    const int h  = blockIdx.y;
    const int b  = blockIdx.z;
    const int tid = threadIdx.x;

    for (int idx = tid; idx < 256 * 16; idx += 256) {
        int s = idx >> 4; int d4 = (idx & 15) << 2;
        size_t off = (size_t)(b * SS + s) * 1024 + h * HDD + d4;
        float4 kvv = *(const float4*)(kv + off);
        Kt[(d4 + 0) * KTP + s] = kvv.x; Kt[(d4 + 1) * KTP + s] = kvv.y;
        Kt[(d4 + 2) * KTP + s] = kvv.z; Kt[(d4 + 3) * KTP + s] = kvv.w;
        float4 vvv = *(const float4*)(kv + off + 512);
        Vt[(d4 + 0) * KTP + s] = vvv.x; Vt[(d4 + 1) * KTP + s] = vvv.y;
        Vt[(d4 + 2) * KTP + s] = vvv.z; Vt[(d4 + 3) * KTP + s] = vvv.w;
    }
    for (int idx = tid; idx < 32 * 16; idx += 256) {
        int r = idx >> 4; int d4 = (idx & 15) << 2;
        int trow = t0 + r;
        float4 qv = make_float4(0.f, 0.f, 0.f, 0.f);
        if (trow < TT)
            qv = *(const float4*)(q + (size_t)(b * TT + trow) * HH + h * HDD + d4);
        float* d = qs + r * QSP + d4;
        d[0] = qv.x; d[1] = qv.y; d[2] = qv.z; d[3] = qv.w;
    }
    __syncthreads();

    const int r  = tid >> 3;
    const int lc = tid & 7;

    float qreg[64];
    #pragma unroll
    for (int d = 0; d < 64; d++) qreg[d] = qs[r * QSP + d];

    float sc[32];
    for (int si = 0; si < 32; si++) {
        int s = si * 8 + lc;
        float acc = 0.f;
        #pragma unroll
        for (int d = 0; d < 64; d++) acc += qreg[d] * Kt[d * KTP + s];
        sc[si] = acc * 0.125f;
    }
    float m = -1e30f;
    #pragma unroll
    for (int si = 0; si < 32; si++) m = fmaxf(m, sc[si]);
    m = fmaxf(m, __shfl_xor_sync(0xffffffff, m, 1));
    m = fmaxf(m, __shfl_xor_sync(0xffffffff, m, 2));
    m = fmaxf(m, __shfl_xor_sync(0xffffffff, m, 4));
    float ssum = 0.f;
    #pragma unroll
    for (int si = 0; si < 32; si++) {
        float e = __expf(sc[si] - m);
        ssum += e;
        ps[r * PSP + si * 8 + lc] = e;
    }
    ssum += __shfl_xor_sync(0xffffffff, ssum, 1);
    ssum += __shfl_xor_sync(0xffffffff, ssum, 2);
    ssum += __shfl_xor_sync(0xffffffff, ssum, 4);
    if (lc == 0) sums[r] = ssum;
    __syncthreads();

    float accv[8];
    #pragma unroll
    for (int j = 0; j < 8; j++) accv[j] = 0.f;
    const float* prow = ps + r * PSP;
    #pragma unroll 4
    for (int s = 0; s < 256; s++) {
        float pv = prow[s];
        #pragma unroll
        for (int j = 0; j < 8; j++)
            accv[j] += pv * Vt[(lc + 8 * j) * KTP + s];
    }
    float inv = 1.0f / sums[r];
    int trow = t0 + r;
    if (trow < TT) {
        float* dst = ctx + (size_t)(b * TT + trow) * HH + h * HDD;
        #pragma unroll
        for (int j = 0; j < 8; j++) dst[lc + 8 * j] = accv[j] * inv;
    }
}

// ---------------- launch ----------------
extern "C" void kernel_launch(void* const* d_in, const int* in_sizes, int n_in,
                              void* d_out, int out_size) {
    const int*   targets  = (const int*)  d_in[0];
    const float* enc      = (const float*)d_in[1];
    const float* embedding= (const float*)d_in[2];
    const float* w_ih     = (const float*)d_in[3];
    const float* w_hh     = (const float*)d_in[4];
    const float* b_ih     = (const float*)d_in[5];
    const float* b_hh     = (const float*)d_in[6];
    const float* in_proj_w= (const float*)d_in[7];
    const float* in_proj_b= (const float*)d_in[8];
    const float* out_proj_w=(const float*)d_in[9];
    const float* out_proj_b=(const float*)d_in[10];
    const float* fc_w     = (const float*)d_in[11];
    const float* fc_b     = (const float*)d_in[12];
    float* out = (float*)d_out;

    float *p_xg, *p_lstm, *p_q, *p_kv, *p_ctx, *p_comb;
    cudaGetSymbolAddress((void**)&p_xg,   g_xg);
    cudaGetSymbolAddress((void**)&p_lstm, g_lstm);
    cudaGetSymbolAddress((void**)&p_q,    g_q);
    cudaGetSymbolAddress((void**)&p_kv,   g_kv);
    cudaGetSymbolAddress((void**)&p_ctx,  g_ctx);
    cudaGetSymbolAddress((void**)&p_comb, g_comb);
    __nv_bfloat16 *p_embh, *p_embl, *p_lstmh, *p_lstml, *p_ctxh, *p_ctxl,
                  *p_combh, *p_combl, *p_ench, *p_encl, *p_wihh, *p_wihl,
                  *p_whhh, *p_whhl, *p_inph, *p_inpl, *p_outph, *p_outpl,
                  *p_fcwh, *p_fcwl;
    cudaGetSymbolAddress((void**)&p_embh,  g_embh);
    cudaGetSymbolAddress((void**)&p_embl,  g_embl);
    cudaGetSymbolAddress((void**)&p_lstmh, g_lstmh);
    cudaGetSymbolAddress((void**)&p_lstml, g_lstml);
    cudaGetSymbolAddress((void**)&p_ctxh,  g_ctxh);
    cudaGetSymbolAddress((void**)&p_ctxl,  g_ctxl);
    cudaGetSymbolAddress((void**)&p_combh, g_combh);
    cudaGetSymbolAddress((void**)&p_combl, g_combl);
    cudaGetSymbolAddress((void**)&p_ench,  g_ench);
    cudaGetSymbolAddress((void**)&p_encl,  g_encl);
    cudaGetSymbolAddress((void**)&p_wihh,  g_wihh);
    cudaGetSymbolAddress((void**)&p_wihl,  g_wihl);
    cudaGetSymbolAddress((void**)&p_whhh,  g_whhh);
    cudaGetSymbolAddress((void**)&p_whhl,  g_whhl);
    cudaGetSymbolAddress((void**)&p_inph,  g_inph);
    cudaGetSymbolAddress((void**)&p_inpl,  g_inpl);
    cudaGetSymbolAddress((void**)&p_outph, g_outph);
    cudaGetSymbolAddress((void**)&p_outpl, g_outpl);
    cudaGetSymbolAddress((void**)&p_fcwh,  g_fcwh);
    cudaGetSymbolAddress((void**)&p_fcwl,  g_fcwl);

    const int attn_smem = (64 * KTP * 2 + 32 * QSP + 32 * PSP + 32) * (int)sizeof(float);
    const int mma_smem  = 8 * SEG;
    cudaFuncSetAttribute(attn_kernel,     cudaFuncAttributeMaxDynamicSharedMemorySize, attn_smem);
    cudaFuncSetAttribute(mma_gemm,        cudaFuncAttributeMaxDynamicSharedMemorySize, mma_smem);
    cudaFuncSetAttribute(lstm_mma_kernel, cudaFuncAttributeMaxDynamicSharedMemorySize, LSTM_SMEM);

    #define SPLIT(src, hi, lo, n) split_kernel<<<((n)/4 + 255) / 256, 256>>>(src, hi, lo, n)

    // 1. zero h0 + flags
    zero_kernel<<<(2 * 4 * 4096 + 255) / 256, 256>>>();

    // 2. weight/input splits
    SPLIT(w_ih,       p_wihh,  p_wihl,  4 * HH * HH);
    SPLIT(w_hh,       p_whhh,  p_whhl,  4 * HH * HH);
    SPLIT(in_proj_w,  p_inph,  p_inpl,  3 * HH * HH);
    SPLIT(out_proj_w, p_outph, p_outpl, HH * HH);
    SPLIT(fc_w,       p_fcwh,  p_fcwl,  VV * HH);
    SPLIT(enc,        p_ench,  p_encl,  BS * HH);

    // 3. gather embeddings (fused split)
    gather_split_kernel<<<BT, 128>>>(targets, embedding, p_embh, p_embl);

    // 4. xg = emb @ w_ih^T + b_ih + b_hh
    {
        dim3 grid(4 * HH / 128, MPAD / 128);
        mma_gemm<<<grid, 256, mma_smem>>>(p_embh, p_embl, p_wihh, p_wihl,
                                          b_ih, b_hh, nullptr, p_xg, BT, 4 * HH, HH);
    }

    // 5. LSTM recurrence + one split afterwards
    lstm_mma_kernel<<<NBLK, 512, LSTM_SMEM>>>(p_xg, p_whhh, p_whhl, p_lstm);
    SPLIT(p_lstm, p_lstmh, p_lstml, BT * HH);

    // 6. q projection + merged K|V projection
    {
        dim3 gq(HH / 128, MPAD / 128);
        mma_gemm<<<gq, 256, mma_smem>>>(p_lstmh, p_lstml, p_inph, p_inpl,
                                        in_proj_b, nullptr, nullptr, p_q, BT, HH, HH);
        dim3 gkv(1024 / 128, BS / 128);
        mma_gemm<<<gkv, 256, mma_smem>>>(p_ench, p_encl, p_inph + (size_t)HH * HH,
                                         p_inpl + (size_t)HH * HH,
                                         in_proj_b + HH, nullptr, nullptr, p_kv,
                                         BS, 1024, HH);
    }

    // 7. fused attention -> fp32 ctx, then split (R11 structure)
    {
        dim3 grid(4, NHH, BB);
        attn_kernel<<<grid, 256, attn_smem>>>(p_q, p_kv, p_ctx);
    }
    SPLIT(p_ctx, p_ctxh, p_ctxl, BT * HH);

    // 8. combined = ctx @ out_proj^T + out_proj_b + lstm_out (fp32), then split
    {
        dim3 grid(HH / 128, MPAD / 128);
        mma_gemm<<<grid, 256, mma_smem>>>(p_ctxh, p_ctxl, p_outph, p_outpl,
                                          out_proj_b, nullptr, p_lstm, p_comb, BT, HH, HH);
    }
    SPLIT(p_comb, p_combh, p_combl, BT * HH);

    // 9. out = combined @ fc_w^T + fc_b
    {
        dim3 grid(VPAD / 128, MPAD / 128);
        mma_gemm<<<grid, 256, mma_smem>>>(p_combh, p_combl, p_fcwh, p_fcwl,
                                          fc_b, nullptr, nullptr, out, BT, VV, HH);
    }
    #undef SPLIT
}